// round 2
// baseline (speedup 1.0000x reference)
#include <cuda_runtime.h>
#include <cstddef>

#define BB 8
#define CC 256
#define NN 2304            // 48*48
#define NPIX ((size_t)BB*CC*NN)

// ---------------- scratch (static device memory: allowed) ----------------
__device__ float g_k[BB*CC*NN];
__device__ float g_q[BB*CC*NN];
__device__ float g_v[BB*CC*NN];
__device__ float g_attn[BB*CC*NN];
__device__ float g_y[BB*CC*NN];
__device__ float g_s[(size_t)BB*NN*NN];   // 170 MB scores/probs
__device__ float g_mean[CC];
__device__ float g_rstd[CC];

// =========================================================================
// GEMM: out[b,o,n] = sum_c W[o,c] * in[b,c,n] (+ bias[o])
// tiles: 128(o) x 128(n) x 16(c); 256 threads; 8x8 micro-tile
// =========================================================================
__global__ __launch_bounds__(256) void gemm_wx(
    const float* __restrict__ Wm, const float* __restrict__ in,
    const float* __restrict__ bias, float* __restrict__ out)
{
    __shared__ __align__(16) float Ws[16][132];   // [c][o]
    __shared__ __align__(16) float Xs[16][132];   // [c][n]
    const int b  = blockIdx.z;
    const int o0 = blockIdx.y * 128;
    const int n0 = blockIdx.x * 128;
    const float* inb  = in  + (size_t)b*CC*NN;
    float*       outb = out + (size_t)b*CC*NN;
    const int tid = threadIdx.x;
    const int tm = tid >> 4;     // 0..15 (o groups)
    const int tn = tid & 15;     // 0..15 (n groups)

    float acc[8][8];
#pragma unroll
    for (int i = 0; i < 8; i++)
#pragma unroll
        for (int j = 0; j < 8; j++) acc[i][j] = 0.f;

    for (int c0 = 0; c0 < CC; c0 += 16) {
#pragma unroll
        for (int i = 0; i < 8; i++) {           // W tile 128x16 -> transposed
            int e = tid + i*256;
            int oo = e >> 4, cc2 = e & 15;
            Ws[cc2][oo] = Wm[(o0+oo)*CC + c0 + cc2];
        }
#pragma unroll
        for (int i = 0; i < 8; i++) {           // X tile 16x128, coalesced rows
            int e = tid + i*256;
            int cc2 = e >> 7, nn2 = e & 127;
            Xs[cc2][nn2] = inb[(size_t)(c0+cc2)*NN + n0 + nn2];
        }
        __syncthreads();
#pragma unroll
        for (int kk = 0; kk < 16; kk++) {
            float a[8], bv[8];
            *(float4*)&a[0]  = *(const float4*)&Ws[kk][tm*8];
            *(float4*)&a[4]  = *(const float4*)&Ws[kk][tm*8+4];
            *(float4*)&bv[0] = *(const float4*)&Xs[kk][tn*8];
            *(float4*)&bv[4] = *(const float4*)&Xs[kk][tn*8+4];
#pragma unroll
            for (int i = 0; i < 8; i++)
#pragma unroll
                for (int j = 0; j < 8; j++)
                    acc[i][j] += a[i]*bv[j];
        }
        __syncthreads();
    }
#pragma unroll
    for (int i = 0; i < 8; i++) {
        int o = o0 + tm*8 + i;
        float bo = bias ? bias[o] : 0.f;
        float4 r0, r1;
        r0.x = acc[i][0]+bo; r0.y = acc[i][1]+bo; r0.z = acc[i][2]+bo; r0.w = acc[i][3]+bo;
        r1.x = acc[i][4]+bo; r1.y = acc[i][5]+bo; r1.z = acc[i][6]+bo; r1.w = acc[i][7]+bo;
        *(float4*)&outb[(size_t)o*NN + n0 + tn*8]     = r0;
        *(float4*)&outb[(size_t)o*NN + n0 + tn*8 + 4] = r1;
    }
}

// =========================================================================
// scores[b,n,m] = sum_c k[b,c,n] * q[b,c,m]
// tiles: 128(n) x 128(m) x 16(c)
// =========================================================================
__global__ __launch_bounds__(256) void scores_kernel()
{
    __shared__ __align__(16) float Ks[16][132];   // [c][n]
    __shared__ __align__(16) float Qs[16][132];   // [c][m]
    const int b  = blockIdx.z;
    const int n0 = blockIdx.y * 128;
    const int m0 = blockIdx.x * 128;
    const float* kb = g_k + (size_t)b*CC*NN;
    const float* qb = g_q + (size_t)b*CC*NN;
    const int tid = threadIdx.x;
    const int tm = tid >> 4;     // n groups
    const int tn = tid & 15;     // m groups

    float acc[8][8];
#pragma unroll
    for (int i = 0; i < 8; i++)
#pragma unroll
        for (int j = 0; j < 8; j++) acc[i][j] = 0.f;

    for (int c0 = 0; c0 < CC; c0 += 16) {
#pragma unroll
        for (int i = 0; i < 8; i++) {
            int e = tid + i*256;
            int cc2 = e >> 7, xx = e & 127;
            Ks[cc2][xx] = kb[(size_t)(c0+cc2)*NN + n0 + xx];
        }
#pragma unroll
        for (int i = 0; i < 8; i++) {
            int e = tid + i*256;
            int cc2 = e >> 7, xx = e & 127;
            Qs[cc2][xx] = qb[(size_t)(c0+cc2)*NN + m0 + xx];
        }
        __syncthreads();
#pragma unroll
        for (int kk = 0; kk < 16; kk++) {
            float a[8], bv[8];
            *(float4*)&a[0]  = *(const float4*)&Ks[kk][tm*8];
            *(float4*)&a[4]  = *(const float4*)&Ks[kk][tm*8+4];
            *(float4*)&bv[0] = *(const float4*)&Qs[kk][tn*8];
            *(float4*)&bv[4] = *(const float4*)&Qs[kk][tn*8+4];
#pragma unroll
            for (int i = 0; i < 8; i++)
#pragma unroll
                for (int j = 0; j < 8; j++)
                    acc[i][j] += a[i]*bv[j];
        }
        __syncthreads();
    }
#pragma unroll
    for (int i = 0; i < 8; i++) {
        float* row = g_s + ((size_t)b*NN + n0 + tm*8 + i) * NN + m0;
        float4 r0 = make_float4(acc[i][0],acc[i][1],acc[i][2],acc[i][3]);
        float4 r1 = make_float4(acc[i][4],acc[i][5],acc[i][6],acc[i][7]);
        *(float4*)&row[tn*8]     = r0;
        *(float4*)&row[tn*8 + 4] = r1;
    }
}

// =========================================================================
// softmax over m (in place on g_s). One block per (b,n) row. 2304 = 256*9
// =========================================================================
__global__ __launch_bounds__(256) void softmax_kernel()
{
    const int b = blockIdx.y, n = blockIdx.x;
    float* row = g_s + ((size_t)b*NN + n) * NN;
    const int tid = threadIdx.x;
    float v[9];
    float mx = -1e30f;
#pragma unroll
    for (int i = 0; i < 9; i++) { v[i] = row[tid + i*256]; mx = fmaxf(mx, v[i]); }

    __shared__ float red[8];
#pragma unroll
    for (int off = 16; off; off >>= 1) mx = fmaxf(mx, __shfl_xor_sync(0xffffffffu, mx, off));
    if ((tid & 31) == 0) red[tid >> 5] = mx;
    __syncthreads();
    float gmx = red[0];
#pragma unroll
    for (int i = 1; i < 8; i++) gmx = fmaxf(gmx, red[i]);

    float s = 0.f;
#pragma unroll
    for (int i = 0; i < 9; i++) { v[i] = __expf(v[i] - gmx); s += v[i]; }
    __syncthreads();
#pragma unroll
    for (int off = 16; off; off >>= 1) s += __shfl_xor_sync(0xffffffffu, s, off);
    if ((tid & 31) == 0) red[tid >> 5] = s;
    __syncthreads();
    float tot = 0.f;
#pragma unroll
    for (int i = 0; i < 8; i++) tot += red[i];
    float inv = 1.0f / tot;
#pragma unroll
    for (int i = 0; i < 9; i++) row[tid + i*256] = v[i] * inv;
}

// =========================================================================
// attn[b,c,n] = sum_m P[b,n,m] * v[b,c,m]
// tiles: 128(c) x 128(n) x 16(m); K-loop length 144
// =========================================================================
__global__ __launch_bounds__(256) void pv_kernel()
{
    __shared__ __align__(16) float Vs[16][132];   // [m][c]
    __shared__ __align__(16) float Ps[16][132];   // [m][n]
    const int b  = blockIdx.z;
    const int c0 = blockIdx.y * 128;
    const int n0 = blockIdx.x * 128;
    const float* vb = g_v + (size_t)b*CC*NN;
    const float* sb = g_s + (size_t)b*NN*NN;
    const int tid = threadIdx.x;
    const int tm = tid >> 4;     // c groups
    const int tn = tid & 15;     // n groups

    float acc[8][8];
#pragma unroll
    for (int i = 0; i < 8; i++)
#pragma unroll
        for (int j = 0; j < 8; j++) acc[i][j] = 0.f;

    for (int m0 = 0; m0 < NN; m0 += 16) {
#pragma unroll
        for (int i = 0; i < 8; i++) {           // V tile (128c x 16m) -> [m][c]
            int e = tid + i*256;
            int ccx = e >> 4, mm = e & 15;
            Vs[mm][ccx] = vb[(size_t)(c0+ccx)*NN + m0 + mm];
        }
#pragma unroll
        for (int i = 0; i < 8; i++) {           // P tile (128n x 16m) -> [m][n]
            int e = tid + i*256;
            int nnx = e >> 4, mm = e & 15;
            Ps[mm][nnx] = sb[(size_t)(n0+nnx)*NN + m0 + mm];
        }
        __syncthreads();
#pragma unroll
        for (int kk = 0; kk < 16; kk++) {
            float a[8], bv[8];
            *(float4*)&a[0]  = *(const float4*)&Vs[kk][tm*8];
            *(float4*)&a[4]  = *(const float4*)&Vs[kk][tm*8+4];
            *(float4*)&bv[0] = *(const float4*)&Ps[kk][tn*8];
            *(float4*)&bv[4] = *(const float4*)&Ps[kk][tn*8+4];
#pragma unroll
            for (int i = 0; i < 8; i++)
#pragma unroll
                for (int j = 0; j < 8; j++)
                    acc[i][j] += a[i]*bv[j];
        }
        __syncthreads();
    }
#pragma unroll
    for (int i = 0; i < 8; i++) {
        float* row = g_attn + ((size_t)b*CC + c0 + tm*8 + i) * NN + n0;
        float4 r0 = make_float4(acc[i][0],acc[i][1],acc[i][2],acc[i][3]);
        float4 r1 = make_float4(acc[i][4],acc[i][5],acc[i][6],acc[i][7]);
        *(float4*)&row[tn*8]     = r0;
        *(float4*)&row[tn*8 + 4] = r1;
    }
}

// =========================================================================
// BatchNorm stats: one block per channel; reduce over B*N = 18432 values
// =========================================================================
__global__ __launch_bounds__(256) void bnstats_kernel()
{
    const int o = blockIdx.x;
    const int tid = threadIdx.x;
    float s1 = 0.f, s2 = 0.f;
    for (int b = 0; b < BB; b++) {
        const float* yr = g_y + ((size_t)b*CC + o) * NN;
        for (int i = tid; i < NN; i += 256) {
            float t = yr[i];
            s1 += t; s2 += t*t;
        }
    }
    __shared__ float r1[8], r2[8];
#pragma unroll
    for (int off = 16; off; off >>= 1) {
        s1 += __shfl_xor_sync(0xffffffffu, s1, off);
        s2 += __shfl_xor_sync(0xffffffffu, s2, off);
    }
    if ((tid & 31) == 0) { r1[tid>>5] = s1; r2[tid>>5] = s2; }
    __syncthreads();
    if (tid == 0) {
        float S1 = 0.f, S2 = 0.f;
#pragma unroll
        for (int i = 0; i < 8; i++) { S1 += r1[i]; S2 += r2[i]; }
        const float invM = 1.0f / (float)(BB*NN);
        float mean = S1 * invM;
        float var  = S2 * invM - mean*mean;
        g_mean[o] = mean;
        g_rstd[o] = rsqrtf(var + 1e-5f);
    }
}

// =========================================================================
// normalize + affine -> d_out
// =========================================================================
__global__ __launch_bounds__(256) void bnorm_kernel(
    const float* __restrict__ gamma, const float* __restrict__ beta,
    float* __restrict__ out)
{
    const int b = blockIdx.z, o = blockIdx.y;
    const int n = blockIdx.x * 256 + threadIdx.x;
    const size_t idx = ((size_t)b*CC + o) * NN + n;
    out[idx] = (g_y[idx] - g_mean[o]) * g_rstd[o] * gamma[o] + beta[o];
}

// =========================================================================
extern "C" void kernel_launch(void* const* d_in, const int* in_sizes, int n_in,
                              void* d_out, int out_size)
{
    (void)in_sizes; (void)n_in; (void)out_size;
    const float* x     = (const float*)d_in[0];
    const float* Wk    = (const float*)d_in[1];
    const float* Wq    = (const float*)d_in[2];
    const float* Wv    = (const float*)d_in[3];
    const float* W2    = (const float*)d_in[4];
    const float* b2    = (const float*)d_in[5];
    const float* gamma = (const float*)d_in[6];
    const float* beta  = (const float*)d_in[7];
    float* out = (float*)d_out;

    float *pk, *pq, *pv, *pattn, *py;
    cudaGetSymbolAddress((void**)&pk,    g_k);
    cudaGetSymbolAddress((void**)&pq,    g_q);
    cudaGetSymbolAddress((void**)&pv,    g_v);
    cudaGetSymbolAddress((void**)&pattn, g_attn);
    cudaGetSymbolAddress((void**)&py,    g_y);

    dim3 blk(256);
    dim3 gWX(NN/128, CC/128, BB);     // (18, 2, 8)
    gemm_wx<<<gWX, blk>>>(Wk, x, nullptr, pk);
    gemm_wx<<<gWX, blk>>>(Wq, x, nullptr, pq);
    gemm_wx<<<gWX, blk>>>(Wv, x, nullptr, pv);

    dim3 gS(NN/128, NN/128, BB);      // (18, 18, 8)
    scores_kernel<<<gS, blk>>>();

    softmax_kernel<<<dim3(NN, BB), blk>>>();

    pv_kernel<<<gWX, blk>>>();

    gemm_wx<<<gWX, blk>>>(W2, pattn, b2, py);

    bnstats_kernel<<<CC, blk>>>();

    bnorm_kernel<<<dim3(NN/256, CC, BB), blk>>>(gamma, beta, out);
}

// round 3
// speedup vs baseline: 2.1560x; 2.1560x over previous
#include <cuda_runtime.h>
#include <cuda_bf16.h>
#include <cstddef>
#include <cstdint>

#define BB 8
#define CC 256
#define NN 2304            // 48*48

// ---------------- scratch (static device memory: allowed) ----------------
__device__ __align__(16) float g_k[BB*CC*NN];
__device__ __align__(16) float g_q[BB*CC*NN];
__device__ __align__(16) float g_attn[BB*CC*NN];
__device__ __align__(16) float g_y[BB*CC*NN];
__device__ __align__(16) float g_s[(size_t)BB*NN*NN];   // 170 MB scores
__device__ float g_mean[CC];
__device__ float g_rstd[CC];

// split bf16 operands
__device__ __align__(16) __nv_bfloat16 g_kth[(size_t)BB*NN*CC];  // kT hi  [b][n][c]
__device__ __align__(16) __nv_bfloat16 g_ktl[(size_t)BB*NN*CC];
__device__ __align__(16) __nv_bfloat16 g_qth[(size_t)BB*NN*CC];  // qT hi  [b][m][c]
__device__ __align__(16) __nv_bfloat16 g_qtl[(size_t)BB*NN*CC];
__device__ __align__(16) __nv_bfloat16 g_vh [(size_t)BB*CC*NN];  // v hi   [b][c][m]
__device__ __align__(16) __nv_bfloat16 g_vl [(size_t)BB*CC*NN];
__device__ __align__(16) __nv_bfloat16 g_ph [(size_t)BB*NN*NN];  // P hi   [b][n][m]
__device__ __align__(16) __nv_bfloat16 g_pl [(size_t)BB*NN*NN];

// ---------------- helpers ----------------
__device__ __forceinline__ void split_bf16(float f, __nv_bfloat16& h, __nv_bfloat16& l) {
    h = __float2bfloat16(f);
    l = __float2bfloat16(f - __bfloat162float(h));
}

__device__ __forceinline__ void ldsm4(uint32_t& r0, uint32_t& r1, uint32_t& r2, uint32_t& r3,
                                      const void* p) {
    uint32_t a = (uint32_t)__cvta_generic_to_shared(p);
    asm volatile("ldmatrix.sync.aligned.m8n8.x4.shared.b16 {%0,%1,%2,%3}, [%4];\n"
                 : "=r"(r0), "=r"(r1), "=r"(r2), "=r"(r3) : "r"(a));
}

__device__ __forceinline__ void mma16816(float* c, const uint32_t* a, const uint32_t* b) {
    asm volatile("mma.sync.aligned.m16n8k16.row.col.f32.bf16.bf16.f32 "
                 "{%0,%1,%2,%3}, {%4,%5,%6,%7}, {%8,%9}, {%0,%1,%2,%3};\n"
                 : "+f"(c[0]), "+f"(c[1]), "+f"(c[2]), "+f"(c[3])
                 : "r"(a[0]), "r"(a[1]), "r"(a[2]), "r"(a[3]), "r"(b[0]), "r"(b[1]));
}

// =========================================================================
// fp32 SIMT GEMM: out[b,o,n] = sum_c W[o,c]*in[b,c,n] (+bias)
// =========================================================================
__global__ __launch_bounds__(256) void gemm_wx(
    const float* __restrict__ Wm, const float* __restrict__ in,
    const float* __restrict__ bias, float* __restrict__ out)
{
    __shared__ __align__(16) float Ws[16][132];
    __shared__ __align__(16) float Xs[16][132];
    const int b  = blockIdx.z;
    const int o0 = blockIdx.y * 128;
    const int n0 = blockIdx.x * 128;
    const float* inb  = in  + (size_t)b*CC*NN;
    float*       outb = out + (size_t)b*CC*NN;
    const int tid = threadIdx.x;
    const int tm = tid >> 4, tn = tid & 15;

    float acc[8][8];
#pragma unroll
    for (int i = 0; i < 8; i++)
#pragma unroll
        for (int j = 0; j < 8; j++) acc[i][j] = 0.f;

    for (int c0 = 0; c0 < CC; c0 += 16) {
#pragma unroll
        for (int i = 0; i < 8; i++) {
            int e = tid + i*256;
            int oo = e >> 4, cc2 = e & 15;
            Ws[cc2][oo] = Wm[(o0+oo)*CC + c0 + cc2];
        }
#pragma unroll
        for (int i = 0; i < 8; i++) {
            int e = tid + i*256;
            int cc2 = e >> 7, nn2 = e & 127;
            Xs[cc2][nn2] = inb[(size_t)(c0+cc2)*NN + n0 + nn2];
        }
        __syncthreads();
#pragma unroll
        for (int kk = 0; kk < 16; kk++) {
            float a[8], bv[8];
            *(float4*)&a[0]  = *(const float4*)&Ws[kk][tm*8];
            *(float4*)&a[4]  = *(const float4*)&Ws[kk][tm*8+4];
            *(float4*)&bv[0] = *(const float4*)&Xs[kk][tn*8];
            *(float4*)&bv[4] = *(const float4*)&Xs[kk][tn*8+4];
#pragma unroll
            for (int i = 0; i < 8; i++)
#pragma unroll
                for (int j = 0; j < 8; j++)
                    acc[i][j] += a[i]*bv[j];
        }
        __syncthreads();
    }
#pragma unroll
    for (int i = 0; i < 8; i++) {
        int o = o0 + tm*8 + i;
        float bo = bias ? bias[o] : 0.f;
        float4 r0, r1;
        r0.x = acc[i][0]+bo; r0.y = acc[i][1]+bo; r0.z = acc[i][2]+bo; r0.w = acc[i][3]+bo;
        r1.x = acc[i][4]+bo; r1.y = acc[i][5]+bo; r1.z = acc[i][6]+bo; r1.w = acc[i][7]+bo;
        *(float4*)&outb[(size_t)o*NN + n0 + tn*8]     = r0;
        *(float4*)&outb[(size_t)o*NN + n0 + tn*8 + 4] = r1;
    }
}

// same GEMM but writes split bf16 hi/lo outputs (for v)
__global__ __launch_bounds__(256) void gemm_wx_split(
    const float* __restrict__ Wm, const float* __restrict__ in,
    __nv_bfloat16* __restrict__ outh, __nv_bfloat16* __restrict__ outl)
{
    __shared__ __align__(16) float Ws[16][132];
    __shared__ __align__(16) float Xs[16][132];
    const int b  = blockIdx.z;
    const int o0 = blockIdx.y * 128;
    const int n0 = blockIdx.x * 128;
    const float* inb = in + (size_t)b*CC*NN;
    __nv_bfloat16* oh = outh + (size_t)b*CC*NN;
    __nv_bfloat16* ol = outl + (size_t)b*CC*NN;
    const int tid = threadIdx.x;
    const int tm = tid >> 4, tn = tid & 15;

    float acc[8][8];
#pragma unroll
    for (int i = 0; i < 8; i++)
#pragma unroll
        for (int j = 0; j < 8; j++) acc[i][j] = 0.f;

    for (int c0 = 0; c0 < CC; c0 += 16) {
#pragma unroll
        for (int i = 0; i < 8; i++) {
            int e = tid + i*256;
            int oo = e >> 4, cc2 = e & 15;
            Ws[cc2][oo] = Wm[(o0+oo)*CC + c0 + cc2];
        }
#pragma unroll
        for (int i = 0; i < 8; i++) {
            int e = tid + i*256;
            int cc2 = e >> 7, nn2 = e & 127;
            Xs[cc2][nn2] = inb[(size_t)(c0+cc2)*NN + n0 + nn2];
        }
        __syncthreads();
#pragma unroll
        for (int kk = 0; kk < 16; kk++) {
            float a[8], bv[8];
            *(float4*)&a[0]  = *(const float4*)&Ws[kk][tm*8];
            *(float4*)&a[4]  = *(const float4*)&Ws[kk][tm*8+4];
            *(float4*)&bv[0] = *(const float4*)&Xs[kk][tn*8];
            *(float4*)&bv[4] = *(const float4*)&Xs[kk][tn*8+4];
#pragma unroll
            for (int i = 0; i < 8; i++)
#pragma unroll
                for (int j = 0; j < 8; j++)
                    acc[i][j] += a[i]*bv[j];
        }
        __syncthreads();
    }
#pragma unroll
    for (int i = 0; i < 8; i++) {
        int o = o0 + tm*8 + i;
        __align__(16) __nv_bfloat16 h8[8], l8[8];
#pragma unroll
        for (int j = 0; j < 8; j++) split_bf16(acc[i][j], h8[j], l8[j]);
        *(uint4*)&oh[(size_t)o*NN + n0 + tn*8] = *(uint4*)h8;
        *(uint4*)&ol[(size_t)o*NN + n0 + tn*8] = *(uint4*)l8;
    }
}

// =========================================================================
// transpose + split-convert: g_k/g_q [b][c][n] fp32 -> kT/qT hi,lo [b][n][c]
// =========================================================================
__global__ __launch_bounds__(256) void transcvt_kernel()
{
    __shared__ float T[32][33];
    const int b   = blockIdx.z >> 1;
    const int sel = blockIdx.z & 1;
    const float* src = (sel ? g_q : g_k) + (size_t)b*CC*NN;
    __nv_bfloat16* dh = (sel ? g_qth : g_kth) + (size_t)b*NN*CC;
    __nv_bfloat16* dl = (sel ? g_qtl : g_ktl) + (size_t)b*NN*CC;
    const int n0 = blockIdx.x * 32, c0 = blockIdx.y * 32;
    const int tx = threadIdx.x & 31, ty = threadIdx.x >> 5;

#pragma unroll
    for (int j = 0; j < 4; j++)
        T[ty + j*8][tx] = src[(size_t)(c0 + ty + j*8)*NN + n0 + tx];
    __syncthreads();
#pragma unroll
    for (int j = 0; j < 4; j++) {
        float v = T[tx][ty + j*8];
        int n = n0 + ty + j*8;
        __nv_bfloat16 h, l;
        split_bf16(v, h, l);
        dh[(size_t)n*CC + c0 + tx] = h;
        dl[(size_t)n*CC + c0 + tx] = l;
    }
}

// =========================================================================
// split-bf16 tensor-core GEMM: D[M0+r][N0+c] = sum_k A[r][k]*B[c][k]
// A,B given as hi/lo bf16; 3 MMAs per fragment (hi*hi + hi*lo + lo*hi)
// block 128x128, 8 warps (2x4), warp tile 64x32, K-chunk 32
// =========================================================================
__global__ __launch_bounds__(256) void mma_split_gemm(
    const __nv_bfloat16* __restrict__ Ah, const __nv_bfloat16* __restrict__ Al,
    size_t aBatch, int aStride,
    const __nv_bfloat16* __restrict__ Bh, const __nv_bfloat16* __restrict__ Bl,
    size_t bBatch, int bStride,
    float* __restrict__ D, size_t dBatch, int dStride, int Ktot)
{
    __shared__ __align__(16) __nv_bfloat16 As[2][128][40];
    __shared__ __align__(16) __nv_bfloat16 Bs[2][128][40];

    const int b  = blockIdx.z;
    const int M0 = blockIdx.y * 128;
    const int N0 = blockIdx.x * 128;
    const int tid  = threadIdx.x;
    const int lane = tid & 31;
    const int warp = tid >> 5;
    const int wm = warp >> 2;     // 0..1
    const int wn = warp & 3;      // 0..3

    const __nv_bfloat16* Abh = Ah + (size_t)b*aBatch + (size_t)M0*aStride;
    const __nv_bfloat16* Abl = Al + (size_t)b*aBatch + (size_t)M0*aStride;
    const __nv_bfloat16* Bbh = Bh + (size_t)b*bBatch + (size_t)N0*bStride;
    const __nv_bfloat16* Bbl = Bl + (size_t)b*bBatch + (size_t)N0*bStride;

    float acc[4][4][4];
#pragma unroll
    for (int i = 0; i < 4; i++)
#pragma unroll
        for (int j = 0; j < 4; j++)
#pragma unroll
            for (int r = 0; r < 4; r++) acc[i][j][r] = 0.f;

    for (int k0 = 0; k0 < Ktot; k0 += 32) {
#pragma unroll
        for (int it = 0; it < 2; it++) {
            int t = tid + it*256;
            int row = t >> 2;
            int seg = (t & 3) * 8;
            size_t aoff = (size_t)row*aStride + k0 + seg;
            size_t boff = (size_t)row*bStride + k0 + seg;
            *(uint4*)&As[0][row][seg] = *(const uint4*)(Abh + aoff);
            *(uint4*)&As[1][row][seg] = *(const uint4*)(Abl + aoff);
            *(uint4*)&Bs[0][row][seg] = *(const uint4*)(Bbh + boff);
            *(uint4*)&Bs[1][row][seg] = *(const uint4*)(Bbl + boff);
        }
        __syncthreads();

#pragma unroll
        for (int kk = 0; kk < 32; kk += 16) {
            uint32_t Af[2][4][4];
#pragma unroll
            for (int mi = 0; mi < 4; mi++) {
                int r = wm*64 + mi*16 + (lane & 15);
                int c = kk + ((lane >> 4) << 3);
                ldsm4(Af[0][mi][0], Af[0][mi][1], Af[0][mi][2], Af[0][mi][3], &As[0][r][c]);
                ldsm4(Af[1][mi][0], Af[1][mi][1], Af[1][mi][2], Af[1][mi][3], &As[1][r][c]);
            }
            uint32_t Bf[2][4][2];
#pragma unroll
            for (int p = 0; p < 2; p++) {
                int r = wn*32 + p*16 + ((lane >> 4) << 3) + (lane & 7);
                int c = kk + (((lane >> 3) & 1) << 3);
                uint32_t r0, r1, r2, r3;
                ldsm4(r0, r1, r2, r3, &Bs[0][r][c]);
                Bf[0][2*p][0] = r0; Bf[0][2*p][1] = r1;
                Bf[0][2*p+1][0] = r2; Bf[0][2*p+1][1] = r3;
                ldsm4(r0, r1, r2, r3, &Bs[1][r][c]);
                Bf[1][2*p][0] = r0; Bf[1][2*p][1] = r1;
                Bf[1][2*p+1][0] = r2; Bf[1][2*p+1][1] = r3;
            }
#pragma unroll
            for (int mi = 0; mi < 4; mi++)
#pragma unroll
                for (int ni = 0; ni < 4; ni++) {
                    mma16816(acc[mi][ni], Af[0][mi], Bf[0][ni]);
                    mma16816(acc[mi][ni], Af[0][mi], Bf[1][ni]);
                    mma16816(acc[mi][ni], Af[1][mi], Bf[0][ni]);
                }
        }
        __syncthreads();
    }

    float* Db = D + (size_t)b*dBatch;
    const int g = lane >> 2, tg2 = (lane & 3) * 2;
#pragma unroll
    for (int mi = 0; mi < 4; mi++)
#pragma unroll
        for (int ni = 0; ni < 4; ni++) {
            int row = M0 + wm*64 + mi*16 + g;
            int col = N0 + wn*32 + ni*8 + tg2;
            *(float2*)&Db[(size_t)row*dStride + col]     = make_float2(acc[mi][ni][0], acc[mi][ni][1]);
            *(float2*)&Db[(size_t)(row+8)*dStride + col] = make_float2(acc[mi][ni][2], acc[mi][ni][3]);
        }
}

// =========================================================================
// softmax over m of g_s; writes split bf16 probs
// =========================================================================
__global__ __launch_bounds__(256) void softmax_kernel()
{
    const int b = blockIdx.y, n = blockIdx.x;
    const float* row = g_s + ((size_t)b*NN + n) * NN;
    __nv_bfloat16* ph = g_ph + ((size_t)b*NN + n) * NN;
    __nv_bfloat16* pl = g_pl + ((size_t)b*NN + n) * NN;
    const int tid = threadIdx.x;
    float v[9];
    float mx = -1e30f;
#pragma unroll
    for (int i = 0; i < 9; i++) { v[i] = row[tid + i*256]; mx = fmaxf(mx, v[i]); }

    __shared__ float red[8];
#pragma unroll
    for (int off = 16; off; off >>= 1) mx = fmaxf(mx, __shfl_xor_sync(0xffffffffu, mx, off));
    if ((tid & 31) == 0) red[tid >> 5] = mx;
    __syncthreads();
    float gmx = red[0];
#pragma unroll
    for (int i = 1; i < 8; i++) gmx = fmaxf(gmx, red[i]);

    float s = 0.f;
#pragma unroll
    for (int i = 0; i < 9; i++) { v[i] = __expf(v[i] - gmx); s += v[i]; }
    __syncthreads();
#pragma unroll
    for (int off = 16; off; off >>= 1) s += __shfl_xor_sync(0xffffffffu, s, off);
    if ((tid & 31) == 0) red[tid >> 5] = s;
    __syncthreads();
    float tot = 0.f;
#pragma unroll
    for (int i = 0; i < 8; i++) tot += red[i];
    float inv = 1.0f / tot;
#pragma unroll
    for (int i = 0; i < 9; i++) {
        float p = v[i] * inv;
        __nv_bfloat16 h, l;
        split_bf16(p, h, l);
        ph[tid + i*256] = h;
        pl[tid + i*256] = l;
    }
}

// =========================================================================
// BatchNorm stats + normalize
// =========================================================================
__global__ __launch_bounds__(256) void bnstats_kernel()
{
    const int o = blockIdx.x;
    const int tid = threadIdx.x;
    float s1 = 0.f, s2 = 0.f;
    for (int b = 0; b < BB; b++) {
        const float* yr = g_y + ((size_t)b*CC + o) * NN;
        for (int i = tid; i < NN; i += 256) {
            float t = yr[i];
            s1 += t; s2 += t*t;
        }
    }
    __shared__ float r1[8], r2[8];
#pragma unroll
    for (int off = 16; off; off >>= 1) {
        s1 += __shfl_xor_sync(0xffffffffu, s1, off);
        s2 += __shfl_xor_sync(0xffffffffu, s2, off);
    }
    if ((tid & 31) == 0) { r1[tid>>5] = s1; r2[tid>>5] = s2; }
    __syncthreads();
    if (tid == 0) {
        float S1 = 0.f, S2 = 0.f;
#pragma unroll
        for (int i = 0; i < 8; i++) { S1 += r1[i]; S2 += r2[i]; }
        const float invM = 1.0f / (float)(BB*NN);
        float mean = S1 * invM;
        float var  = S2 * invM - mean*mean;
        g_mean[o] = mean;
        g_rstd[o] = rsqrtf(var + 1e-5f);
    }
}

__global__ __launch_bounds__(256) void bnorm_kernel(
    const float* __restrict__ gamma, const float* __restrict__ beta,
    float* __restrict__ out)
{
    const int b = blockIdx.z, o = blockIdx.y;
    const int n = blockIdx.x * 256 + threadIdx.x;
    const size_t idx = ((size_t)b*CC + o) * NN + n;
    out[idx] = (g_y[idx] - g_mean[o]) * g_rstd[o] * gamma[o] + beta[o];
}

// =========================================================================
extern "C" void kernel_launch(void* const* d_in, const int* in_sizes, int n_in,
                              void* d_out, int out_size)
{
    (void)in_sizes; (void)n_in; (void)out_size;
    const float* x     = (const float*)d_in[0];
    const float* Wk    = (const float*)d_in[1];
    const float* Wq    = (const float*)d_in[2];
    const float* Wv    = (const float*)d_in[3];
    const float* W2    = (const float*)d_in[4];
    const float* b2    = (const float*)d_in[5];
    const float* gamma = (const float*)d_in[6];
    const float* beta  = (const float*)d_in[7];
    float* out = (float*)d_out;

    float *pk, *pq, *pattn, *py, *ps;
    __nv_bfloat16 *pkth, *pktl, *pqth, *pqtl, *pvh, *pvl, *pph, *ppl;
    cudaGetSymbolAddress((void**)&pk,    g_k);
    cudaGetSymbolAddress((void**)&pq,    g_q);
    cudaGetSymbolAddress((void**)&pattn, g_attn);
    cudaGetSymbolAddress((void**)&py,    g_y);
    cudaGetSymbolAddress((void**)&ps,    g_s);
    cudaGetSymbolAddress((void**)&pkth,  g_kth);
    cudaGetSymbolAddress((void**)&pktl,  g_ktl);
    cudaGetSymbolAddress((void**)&pqth,  g_qth);
    cudaGetSymbolAddress((void**)&pqtl,  g_qtl);
    cudaGetSymbolAddress((void**)&pvh,   g_vh);
    cudaGetSymbolAddress((void**)&pvl,   g_vl);
    cudaGetSymbolAddress((void**)&pph,   g_ph);
    cudaGetSymbolAddress((void**)&ppl,   g_pl);

    dim3 blk(256);
    dim3 gWX(NN/128, CC/128, BB);     // (18, 2, 8)
    gemm_wx<<<gWX, blk>>>(Wk, x, nullptr, pk);
    gemm_wx<<<gWX, blk>>>(Wq, x, nullptr, pq);
    gemm_wx_split<<<gWX, blk>>>(Wv, x, pvh, pvl);

    transcvt_kernel<<<dim3(NN/32, CC/32, BB*2), blk>>>();

    // scores[b,n,m] = sum_c kT[n,c]*qT[m,c]
    mma_split_gemm<<<dim3(NN/128, NN/128, BB), blk>>>(
        pkth, pktl, (size_t)NN*CC, CC,
        pqth, pqtl, (size_t)NN*CC, CC,
        ps, (size_t)NN*NN, NN, CC);

    softmax_kernel<<<dim3(NN, BB), blk>>>();

    // attn[b,c,n] = sum_m v[c,m]*P[n,m]
    mma_split_gemm<<<dim3(NN/128, CC/128, BB), blk>>>(
        pvh, pvl, (size_t)CC*NN, NN,
        pph, ppl, (size_t)NN*NN, NN,
        pattn, (size_t)CC*NN, NN, NN);

    gemm_wx<<<gWX, blk>>>(W2, pattn, b2, py);

    bnstats_kernel<<<CC, blk>>>();

    bnorm_kernel<<<dim3(NN/256, CC, BB), blk>>>(gamma, beta, out);
}

// round 4
// speedup vs baseline: 2.1740x; 1.0084x over previous
#include <cuda_runtime.h>
#include <cuda_bf16.h>
#include <cstddef>
#include <cstdint>

#define BB 8
#define CC 256
#define NN 2304            // 48*48

// ---------------- scratch (static device memory: allowed) ----------------
__device__ __align__(16) float g_s[(size_t)BB*NN*NN];   // 170 MB scores
__device__ __align__(16) float g_y[(size_t)BB*NN*CC];   // y in [b][n][o]
__device__ float g_mean[CC];
__device__ float g_rstd[CC];

// split bf16 operands
__device__ __align__(16) __nv_bfloat16 g_xth[(size_t)BB*NN*CC], g_xtl[(size_t)BB*NN*CC]; // xT [b][n][c]
__device__ __align__(16) __nv_bfloat16 g_kth[(size_t)BB*NN*CC], g_ktl[(size_t)BB*NN*CC]; // kT [b][n][c]
__device__ __align__(16) __nv_bfloat16 g_qth[(size_t)BB*NN*CC], g_qtl[(size_t)BB*NN*CC]; // qT [b][m][c]
__device__ __align__(16) __nv_bfloat16 g_vh [(size_t)BB*CC*NN], g_vl [(size_t)BB*CC*NN]; // v  [b][c][m]
__device__ __align__(16) __nv_bfloat16 g_ath[(size_t)BB*NN*CC], g_atl[(size_t)BB*NN*CC]; // attnT [b][n][c]
__device__ __align__(16) __nv_bfloat16 g_ph [(size_t)BB*NN*NN], g_pl [(size_t)BB*NN*NN]; // P [b][n][m]
__device__ __align__(16) __nv_bfloat16 g_wkh[CC*CC], g_wkl[CC*CC];
__device__ __align__(16) __nv_bfloat16 g_wqh[CC*CC], g_wql[CC*CC];
__device__ __align__(16) __nv_bfloat16 g_wvh[CC*CC], g_wvl[CC*CC];
__device__ __align__(16) __nv_bfloat16 g_w2h[CC*CC], g_w2l[CC*CC];

// ---------------- helpers ----------------
__device__ __forceinline__ void split_bf16(float f, __nv_bfloat16& h, __nv_bfloat16& l) {
    h = __float2bfloat16(f);
    l = __float2bfloat16(f - __bfloat162float(h));
}

__device__ __forceinline__ void ldsm4(uint32_t& r0, uint32_t& r1, uint32_t& r2, uint32_t& r3,
                                      const void* p) {
    uint32_t a = (uint32_t)__cvta_generic_to_shared(p);
    asm volatile("ldmatrix.sync.aligned.m8n8.x4.shared.b16 {%0,%1,%2,%3}, [%4];\n"
                 : "=r"(r0), "=r"(r1), "=r"(r2), "=r"(r3) : "r"(a));
}

__device__ __forceinline__ void mma16816(float* c, const uint32_t* a, const uint32_t* b) {
    asm volatile("mma.sync.aligned.m16n8k16.row.col.f32.bf16.bf16.f32 "
                 "{%0,%1,%2,%3}, {%4,%5,%6,%7}, {%8,%9}, {%0,%1,%2,%3};\n"
                 : "+f"(c[0]), "+f"(c[1]), "+f"(c[2]), "+f"(c[3])
                 : "r"(a[0]), "r"(a[1]), "r"(a[2]), "r"(a[3]), "r"(b[0]), "r"(b[1]));
}

__device__ __forceinline__ void cpasync16(void* s, const void* g) {
    uint32_t a = (uint32_t)__cvta_generic_to_shared(s);
    asm volatile("cp.async.cg.shared.global [%0], [%1], 16;\n" :: "r"(a), "l"(g));
}
__device__ __forceinline__ void cp_commit() { asm volatile("cp.async.commit_group;\n" ::); }

// =========================================================================
// split-bf16 tensor-core GEMM: D[b][M0+r][N0+c] = sum_k A[r][k]*B[c][k]
// 3 MMAs per fragment (hi*hi + hi*lo + lo*hi).
// block 128x128, 8 warps (2x4), warp tile 64x32, K-chunk 32, 2-stage cp.async.
// Epilogue: fp32 D (+bias[col]) if Df != nullptr, else split bf16 Dh/Dl.
// =========================================================================
__global__ __launch_bounds__(256) void mma_split_gemm(
    const __nv_bfloat16* __restrict__ Ah, const __nv_bfloat16* __restrict__ Al,
    size_t aBatch, int aStride,
    const __nv_bfloat16* __restrict__ Bh, const __nv_bfloat16* __restrict__ Bl,
    size_t bBatch, int bStride,
    float* __restrict__ Df,
    __nv_bfloat16* __restrict__ Dh, __nv_bfloat16* __restrict__ Dl,
    const float* __restrict__ bias,
    size_t dBatch, int dStride, int Ktot)
{
    extern __shared__ __align__(16) __nv_bfloat16 smem[];
    __nv_bfloat16* Abase = smem;                   // [2 stage][2 hi/lo][128*40]
    __nv_bfloat16* Bbase = smem + 2*2*128*40;
#define AS(s,h) (Abase + ((s)*2+(h))*5120)
#define BS(s,h) (Bbase + ((s)*2+(h))*5120)

    const int b  = blockIdx.z;
    const int M0 = blockIdx.y * 128;
    const int N0 = blockIdx.x * 128;
    const int tid  = threadIdx.x;
    const int lane = tid & 31;
    const int warp = tid >> 5;
    const int wm = warp >> 2;     // 0..1
    const int wn = warp & 3;      // 0..3

    const __nv_bfloat16* Abh = Ah + (size_t)b*aBatch + (size_t)M0*aStride;
    const __nv_bfloat16* Abl = Al + (size_t)b*aBatch + (size_t)M0*aStride;
    const __nv_bfloat16* Bbh = Bh + (size_t)b*bBatch + (size_t)N0*bStride;
    const __nv_bfloat16* Bbl = Bl + (size_t)b*bBatch + (size_t)N0*bStride;

    float acc[4][4][4];
#pragma unroll
    for (int i = 0; i < 4; i++)
#pragma unroll
        for (int j = 0; j < 4; j++)
#pragma unroll
            for (int r = 0; r < 4; r++) acc[i][j][r] = 0.f;

    const int T = Ktot >> 5;   // K chunks of 32

    // prologue: load stage 0
    {
#pragma unroll
        for (int it = 0; it < 2; it++) {
            int t = tid + it*256;
            int row = t >> 2, seg = (t & 3) * 8;
            cpasync16(AS(0,0)+row*40+seg, Abh + (size_t)row*aStride + seg);
            cpasync16(AS(0,1)+row*40+seg, Abl + (size_t)row*aStride + seg);
            cpasync16(BS(0,0)+row*40+seg, Bbh + (size_t)row*bStride + seg);
            cpasync16(BS(0,1)+row*40+seg, Bbl + (size_t)row*bStride + seg);
        }
        cp_commit();
    }

    for (int t = 0; t < T; t++) {
        const int cur = t & 1;
        if (t + 1 < T) {
            const int nxt = cur ^ 1;
            const int k0 = (t + 1) << 5;
#pragma unroll
            for (int it = 0; it < 2; it++) {
                int e = tid + it*256;
                int row = e >> 2, seg = (e & 3) * 8;
                cpasync16(AS(nxt,0)+row*40+seg, Abh + (size_t)row*aStride + k0 + seg);
                cpasync16(AS(nxt,1)+row*40+seg, Abl + (size_t)row*aStride + k0 + seg);
                cpasync16(BS(nxt,0)+row*40+seg, Bbh + (size_t)row*bStride + k0 + seg);
                cpasync16(BS(nxt,1)+row*40+seg, Bbl + (size_t)row*bStride + k0 + seg);
            }
            cp_commit();
            asm volatile("cp.async.wait_group 1;\n" ::);
        } else {
            asm volatile("cp.async.wait_group 0;\n" ::);
        }
        __syncthreads();

#pragma unroll
        for (int kk = 0; kk < 32; kk += 16) {
            uint32_t Af[2][4][4];
#pragma unroll
            for (int mi = 0; mi < 4; mi++) {
                int r = wm*64 + mi*16 + (lane & 15);
                int c = kk + ((lane >> 4) << 3);
                ldsm4(Af[0][mi][0], Af[0][mi][1], Af[0][mi][2], Af[0][mi][3], AS(cur,0)+r*40+c);
                ldsm4(Af[1][mi][0], Af[1][mi][1], Af[1][mi][2], Af[1][mi][3], AS(cur,1)+r*40+c);
            }
            uint32_t Bf[2][4][2];
#pragma unroll
            for (int p = 0; p < 2; p++) {
                int r = wn*32 + p*16 + ((lane >> 4) << 3) + (lane & 7);
                int c = kk + (((lane >> 3) & 1) << 3);
                uint32_t r0, r1, r2, r3;
                ldsm4(r0, r1, r2, r3, BS(cur,0)+r*40+c);
                Bf[0][2*p][0] = r0; Bf[0][2*p][1] = r1;
                Bf[0][2*p+1][0] = r2; Bf[0][2*p+1][1] = r3;
                ldsm4(r0, r1, r2, r3, BS(cur,1)+r*40+c);
                Bf[1][2*p][0] = r0; Bf[1][2*p][1] = r1;
                Bf[1][2*p+1][0] = r2; Bf[1][2*p+1][1] = r3;
            }
#pragma unroll
            for (int mi = 0; mi < 4; mi++)
#pragma unroll
                for (int ni = 0; ni < 4; ni++) {
                    mma16816(acc[mi][ni], Af[0][mi], Bf[0][ni]);
                    mma16816(acc[mi][ni], Af[0][mi], Bf[1][ni]);
                    mma16816(acc[mi][ni], Af[1][mi], Bf[0][ni]);
                }
        }
        __syncthreads();
    }

    const int g = lane >> 2, tg2 = (lane & 3) * 2;
    if (Df) {
        float* Db = Df + (size_t)b*dBatch;
#pragma unroll
        for (int mi = 0; mi < 4; mi++)
#pragma unroll
            for (int ni = 0; ni < 4; ni++) {
                int row = M0 + wm*64 + mi*16 + g;
                int col = N0 + wn*32 + ni*8 + tg2;
                float b0 = bias ? bias[col] : 0.f;
                float b1 = bias ? bias[col+1] : 0.f;
                *(float2*)&Db[(size_t)row*dStride + col] =
                    make_float2(acc[mi][ni][0]+b0, acc[mi][ni][1]+b1);
                *(float2*)&Db[(size_t)(row+8)*dStride + col] =
                    make_float2(acc[mi][ni][2]+b0, acc[mi][ni][3]+b1);
            }
    } else {
        __nv_bfloat16* Dbh = Dh + (size_t)b*dBatch;
        __nv_bfloat16* Dbl = Dl + (size_t)b*dBatch;
#pragma unroll
        for (int mi = 0; mi < 4; mi++)
#pragma unroll
            for (int ni = 0; ni < 4; ni++) {
                int row = M0 + wm*64 + mi*16 + g;
                int col = N0 + wn*32 + ni*8 + tg2;
                __nv_bfloat16 h0,l0,h1,l1;
                __nv_bfloat162 hp, lp;
                split_bf16(acc[mi][ni][0], h0, l0);
                split_bf16(acc[mi][ni][1], h1, l1);
                hp.x = h0; hp.y = h1; lp.x = l0; lp.y = l1;
                *(__nv_bfloat162*)&Dbh[(size_t)row*dStride + col] = hp;
                *(__nv_bfloat162*)&Dbl[(size_t)row*dStride + col] = lp;
                split_bf16(acc[mi][ni][2], h0, l0);
                split_bf16(acc[mi][ni][3], h1, l1);
                hp.x = h0; hp.y = h1; lp.x = l0; lp.y = l1;
                *(__nv_bfloat162*)&Dbh[(size_t)(row+8)*dStride + col] = hp;
                *(__nv_bfloat162*)&Dbl[(size_t)(row+8)*dStride + col] = lp;
            }
    }
#undef AS
#undef BS
}

// =========================================================================
// weight split: W fp32 [count] -> hi/lo bf16
// =========================================================================
__global__ __launch_bounds__(256) void wsplit_kernel(
    const float* __restrict__ W, __nv_bfloat16* __restrict__ h,
    __nv_bfloat16* __restrict__ l)
{
    int i = blockIdx.x * 256 + threadIdx.x;
    split_bf16(W[i], h[i], l[i]);
}

// =========================================================================
// x transpose + split: x [b][c][n] fp32 -> xT hi/lo [b][n][c]
// =========================================================================
__global__ __launch_bounds__(256) void xsplit_kernel(const float* __restrict__ x)
{
    __shared__ float Tm[32][33];
    const int b = blockIdx.z;
    const float* src = x + (size_t)b*CC*NN;
    __nv_bfloat16* dh = g_xth + (size_t)b*NN*CC;
    __nv_bfloat16* dl = g_xtl + (size_t)b*NN*CC;
    const int n0 = blockIdx.x * 32, c0 = blockIdx.y * 32;
    const int tx = threadIdx.x & 31, ty = threadIdx.x >> 5;

#pragma unroll
    for (int j = 0; j < 4; j++)
        Tm[ty + j*8][tx] = src[(size_t)(c0 + ty + j*8)*NN + n0 + tx];
    __syncthreads();
#pragma unroll
    for (int j = 0; j < 4; j++) {
        float v = Tm[tx][ty + j*8];
        int n = n0 + ty + j*8;
        __nv_bfloat16 h, l;
        split_bf16(v, h, l);
        dh[(size_t)n*CC + c0 + tx] = h;
        dl[(size_t)n*CC + c0 + tx] = l;
    }
}

// =========================================================================
// softmax over m of g_s; writes split bf16 probs
// =========================================================================
__global__ __launch_bounds__(256) void softmax_kernel()
{
    const int b = blockIdx.y, n = blockIdx.x;
    const float* row = g_s + ((size_t)b*NN + n) * NN;
    __nv_bfloat16* ph = g_ph + ((size_t)b*NN + n) * NN;
    __nv_bfloat16* pl = g_pl + ((size_t)b*NN + n) * NN;
    const int tid = threadIdx.x;
    float v[9];
    float mx = -1e30f;
#pragma unroll
    for (int i = 0; i < 9; i++) { v[i] = row[tid + i*256]; mx = fmaxf(mx, v[i]); }

    __shared__ float red[8];
#pragma unroll
    for (int off = 16; off; off >>= 1) mx = fmaxf(mx, __shfl_xor_sync(0xffffffffu, mx, off));
    if ((tid & 31) == 0) red[tid >> 5] = mx;
    __syncthreads();
    float gmx = red[0];
#pragma unroll
    for (int i = 1; i < 8; i++) gmx = fmaxf(gmx, red[i]);

    float s = 0.f;
#pragma unroll
    for (int i = 0; i < 9; i++) { v[i] = __expf(v[i] - gmx); s += v[i]; }
    __syncthreads();
#pragma unroll
    for (int off = 16; off; off >>= 1) s += __shfl_xor_sync(0xffffffffu, s, off);
    if ((tid & 31) == 0) red[tid >> 5] = s;
    __syncthreads();
    float tot = 0.f;
#pragma unroll
    for (int i = 0; i < 8; i++) tot += red[i];
    float inv = 1.0f / tot;
#pragma unroll
    for (int i = 0; i < 9; i++) {
        float p = v[i] * inv;
        __nv_bfloat16 h, l;
        split_bf16(p, h, l);
        ph[tid + i*256] = h;
        pl[tid + i*256] = l;
    }
}

// =========================================================================
// BatchNorm stats over y [b][n][o]: reduce (b,n) per channel o
// grid 8 blocks; block 256 = 32(o) x 8(n-stride)
// =========================================================================
__global__ __launch_bounds__(256) void bnstats_kernel()
{
    const int tx = threadIdx.x & 31, ty = threadIdx.x >> 5;
    const int o = blockIdx.x * 32 + tx;
    float s1 = 0.f, s2 = 0.f;
    for (int b = 0; b < BB; b++) {
        const float* yb = g_y + (size_t)b*NN*CC;
        for (int n = ty; n < NN; n += 8) {
            float v = yb[(size_t)n*CC + o];
            s1 += v; s2 += v*v;
        }
    }
    __shared__ float r1[8][32], r2[8][32];
    r1[ty][tx] = s1; r2[ty][tx] = s2;
    __syncthreads();
    if (ty == 0) {
        float S1 = s1, S2 = s2;
#pragma unroll
        for (int i = 1; i < 8; i++) { S1 += r1[i][tx]; S2 += r2[i][tx]; }
        const float invM = 1.0f / (float)(BB*NN);
        float mean = S1 * invM;
        float var  = S2 * invM - mean*mean;
        g_mean[o] = mean;
        g_rstd[o] = rsqrtf(var + 1e-5f);
    }
}

// =========================================================================
// normalize + affine + transpose: y [b][n][o] -> out [b][o][n]
// =========================================================================
__global__ __launch_bounds__(256) void bnorm_kernel(
    const float* __restrict__ gamma, const float* __restrict__ beta,
    float* __restrict__ out)
{
    __shared__ float Tm[32][33];
    const int b = blockIdx.z;
    const int n0 = blockIdx.x * 32, o0 = blockIdx.y * 32;
    const int tx = threadIdx.x & 31, ty = threadIdx.x >> 5;
    const float* yb = g_y + (size_t)b*NN*CC;
#pragma unroll
    for (int j = 0; j < 4; j++)
        Tm[ty + j*8][tx] = yb[(size_t)(n0 + ty + j*8)*CC + o0 + tx];
    __syncthreads();
#pragma unroll
    for (int j = 0; j < 4; j++) {
        int o = o0 + ty + j*8;
        float sc = g_rstd[o] * gamma[o];
        float mb = g_mean[o];
        out[((size_t)b*CC + o)*NN + n0 + tx] = (Tm[tx][ty + j*8] - mb) * sc + beta[o];
    }
}

// =========================================================================
extern "C" void kernel_launch(void* const* d_in, const int* in_sizes, int n_in,
                              void* d_out, int out_size)
{
    (void)in_sizes; (void)n_in; (void)out_size;
    const float* x     = (const float*)d_in[0];
    const float* Wk    = (const float*)d_in[1];
    const float* Wq    = (const float*)d_in[2];
    const float* Wv    = (const float*)d_in[3];
    const float* W2    = (const float*)d_in[4];
    const float* b2    = (const float*)d_in[5];
    const float* gamma = (const float*)d_in[6];
    const float* beta  = (const float*)d_in[7];
    float* out = (float*)d_out;

    float *ps, *py;
    __nv_bfloat16 *pxth,*pxtl,*pkth,*pktl,*pqth,*pqtl,*pvh,*pvl,*path,*patl,*pph,*ppl;
    __nv_bfloat16 *pwkh,*pwkl,*pwqh,*pwql,*pwvh,*pwvl,*pw2h,*pw2l;
    cudaGetSymbolAddress((void**)&ps,   g_s);
    cudaGetSymbolAddress((void**)&py,   g_y);
    cudaGetSymbolAddress((void**)&pxth, g_xth); cudaGetSymbolAddress((void**)&pxtl, g_xtl);
    cudaGetSymbolAddress((void**)&pkth, g_kth); cudaGetSymbolAddress((void**)&pktl, g_ktl);
    cudaGetSymbolAddress((void**)&pqth, g_qth); cudaGetSymbolAddress((void**)&pqtl, g_qtl);
    cudaGetSymbolAddress((void**)&pvh,  g_vh);  cudaGetSymbolAddress((void**)&pvl,  g_vl);
    cudaGetSymbolAddress((void**)&path, g_ath); cudaGetSymbolAddress((void**)&patl, g_atl);
    cudaGetSymbolAddress((void**)&pph,  g_ph);  cudaGetSymbolAddress((void**)&ppl,  g_pl);
    cudaGetSymbolAddress((void**)&pwkh, g_wkh); cudaGetSymbolAddress((void**)&pwkl, g_wkl);
    cudaGetSymbolAddress((void**)&pwqh, g_wqh); cudaGetSymbolAddress((void**)&pwql, g_wql);
    cudaGetSymbolAddress((void**)&pwvh, g_wvh); cudaGetSymbolAddress((void**)&pwvl, g_wvl);
    cudaGetSymbolAddress((void**)&pw2h, g_w2h); cudaGetSymbolAddress((void**)&pw2l, g_w2l);

    const int SMEM = 2*2*128*40*2*2;   // 81920 bytes
    cudaFuncSetAttribute(mma_split_gemm, cudaFuncAttributeMaxDynamicSharedMemorySize, SMEM);

    dim3 blk(256);

    wsplit_kernel<<<CC*CC/256, blk>>>(Wk, pwkh, pwkl);
    wsplit_kernel<<<CC*CC/256, blk>>>(Wq, pwqh, pwql);
    wsplit_kernel<<<CC*CC/256, blk>>>(Wv, pwvh, pwvl);
    wsplit_kernel<<<CC*CC/256, blk>>>(W2, pw2h, pw2l);

    xsplit_kernel<<<dim3(NN/32, CC/32, BB), blk>>>(x);

    // kT[b][n][o] = sum_c xT[n][c] * Wk[o][c]   (split out)
    mma_split_gemm<<<dim3(CC/128, NN/128, BB), blk, SMEM>>>(
        pxth, pxtl, (size_t)NN*CC, CC,  pwkh, pwkl, 0, CC,
        nullptr, pkth, pktl, nullptr, (size_t)NN*CC, CC, CC);
    // qT
    mma_split_gemm<<<dim3(CC/128, NN/128, BB), blk, SMEM>>>(
        pxth, pxtl, (size_t)NN*CC, CC,  pwqh, pwql, 0, CC,
        nullptr, pqth, pqtl, nullptr, (size_t)NN*CC, CC, CC);
    // v[b][c][m] = sum_c' Wv[c][c'] * xT[m][c']   (split out)
    mma_split_gemm<<<dim3(NN/128, CC/128, BB), blk, SMEM>>>(
        pwvh, pwvl, 0, CC,  pxth, pxtl, (size_t)NN*CC, CC,
        nullptr, pvh, pvl, nullptr, (size_t)CC*NN, NN, CC);

    // scores[b][n][m] = sum_c kT[n][c]*qT[m][c]  (fp32 out)
    mma_split_gemm<<<dim3(NN/128, NN/128, BB), blk, SMEM>>>(
        pkth, pktl, (size_t)NN*CC, CC,  pqth, pqtl, (size_t)NN*CC, CC,
        ps, nullptr, nullptr, nullptr, (size_t)NN*NN, NN, CC);

    softmax_kernel<<<dim3(NN, BB), blk>>>();

    // attnT[b][n][c] = sum_m P[n][m]*v[c][m]  (split out)
    mma_split_gemm<<<dim3(CC/128, NN/128, BB), blk, SMEM>>>(
        pph, ppl, (size_t)NN*NN, NN,  pvh, pvl, (size_t)CC*NN, NN,
        nullptr, path, patl, nullptr, (size_t)NN*CC, CC, NN);

    // y[b][n][o] = sum_c attnT[n][c]*W2[o][c] + b2[o]  (fp32 out)
    mma_split_gemm<<<dim3(CC/128, NN/128, BB), blk, SMEM>>>(
        path, patl, (size_t)NN*CC, CC,  pw2h, pw2l, 0, CC,
        py, nullptr, nullptr, b2, (size_t)NN*CC, CC, CC);

    bnstats_kernel<<<CC/32, blk>>>();

    bnorm_kernel<<<dim3(NN/32, CC/32, BB), blk>>>(gamma, beta, out);
}

// round 7
// speedup vs baseline: 2.6939x; 1.2392x over previous
#include <cuda_runtime.h>
#include <cuda_bf16.h>
#include <cstddef>
#include <cstdint>

#define BB 8
#define CC 256
#define NN 2304            // 48*48

// ---------------- scratch (static device memory: allowed) ----------------
__device__ __align__(16) float g_s[(size_t)BB*NN*NN];   // 170 MB scores
__device__ __align__(16) float g_y[(size_t)BB*NN*CC];   // y in [b][n][o]
__device__ float g_mean[CC];
__device__ float g_rstd[CC];
__device__ float g_p1[48][CC];
__device__ float g_p2[48][CC];

// split bf16 operands
__device__ __align__(16) __nv_bfloat16 g_xth[(size_t)BB*NN*CC], g_xtl[(size_t)BB*NN*CC]; // xT [b][n][c]
__device__ __align__(16) __nv_bfloat16 g_kth[(size_t)BB*NN*CC], g_ktl[(size_t)BB*NN*CC]; // kT [b][n][c]
__device__ __align__(16) __nv_bfloat16 g_qth[(size_t)BB*NN*CC], g_qtl[(size_t)BB*NN*CC]; // qT [b][m][c]
__device__ __align__(16) __nv_bfloat16 g_vh [(size_t)BB*CC*NN], g_vl [(size_t)BB*CC*NN]; // v  [b][c][m]
__device__ __align__(16) __nv_bfloat16 g_ath[(size_t)BB*NN*CC], g_atl[(size_t)BB*NN*CC]; // attnT [b][n][c]
__device__ __align__(16) __nv_bfloat16 g_ph [(size_t)BB*NN*NN], g_pl [(size_t)BB*NN*NN]; // P [b][n][m]
__device__ __align__(16) __nv_bfloat16 g_wkh[CC*CC], g_wkl[CC*CC];
__device__ __align__(16) __nv_bfloat16 g_wqh[CC*CC], g_wql[CC*CC];
__device__ __align__(16) __nv_bfloat16 g_wvh[CC*CC], g_wvl[CC*CC];
__device__ __align__(16) __nv_bfloat16 g_w2h[CC*CC], g_w2l[CC*CC];

// ---------------- helpers ----------------
__device__ __forceinline__ void split_bf16(float f, __nv_bfloat16& h, __nv_bfloat16& l) {
    h = __float2bfloat16(f);
    l = __float2bfloat16(f - __bfloat162float(h));
}

__device__ __forceinline__ void ldsm4(uint32_t& r0, uint32_t& r1, uint32_t& r2, uint32_t& r3,
                                      const void* p) {
    uint32_t a = (uint32_t)__cvta_generic_to_shared(p);
    asm volatile("ldmatrix.sync.aligned.m8n8.x4.shared.b16 {%0,%1,%2,%3}, [%4];\n"
                 : "=r"(r0), "=r"(r1), "=r"(r2), "=r"(r3) : "r"(a));
}

__device__ __forceinline__ void mma16816(float* c, const uint32_t* a, const uint32_t* b) {
    asm volatile("mma.sync.aligned.m16n8k16.row.col.f32.bf16.bf16.f32 "
                 "{%0,%1,%2,%3}, {%4,%5,%6,%7}, {%8,%9}, {%0,%1,%2,%3};\n"
                 : "+f"(c[0]), "+f"(c[1]), "+f"(c[2]), "+f"(c[3])
                 : "r"(a[0]), "r"(a[1]), "r"(a[2]), "r"(a[3]), "r"(b[0]), "r"(b[1]));
}

__device__ __forceinline__ void cpasync16(void* s, const void* g) {
    uint32_t a = (uint32_t)__cvta_generic_to_shared(s);
    asm volatile("cp.async.cg.shared.global [%0], [%1], 16;\n" :: "r"(a), "l"(g));
}
__device__ __forceinline__ void cp_commit() { asm volatile("cp.async.commit_group;\n" ::); }

// =========================================================================
// split-bf16 tensor-core GEMM: D[b][M0+r][N0+c] = sum_k A[r][k]*B[c][k]
// 3 MMAs per fragment (hi*hi + hi*lo + lo*hi).
// block 128x128, 8 warps (2x4), warp tile 64x32, K-chunk 32, 2-stage cp.async.
// __launch_bounds__(256,2): cap regs at 128 so 2 CTAs/SM co-reside (160KB smem).
// =========================================================================
__global__ __launch_bounds__(256, 2) void mma_split_gemm(
    const __nv_bfloat16* __restrict__ Ah, const __nv_bfloat16* __restrict__ Al,
    size_t aBatch, int aStride,
    const __nv_bfloat16* __restrict__ Bh, const __nv_bfloat16* __restrict__ Bl,
    size_t bBatch, int bStride,
    float* __restrict__ Df,
    __nv_bfloat16* __restrict__ Dh, __nv_bfloat16* __restrict__ Dl,
    const float* __restrict__ bias,
    size_t dBatch, int dStride, int Ktot)
{
    extern __shared__ __align__(16) __nv_bfloat16 smem[];
    __nv_bfloat16* Abase = smem;                   // [2 stage][2 hi/lo][128*40]
    __nv_bfloat16* Bbase = smem + 2*2*128*40;
#define AS(s,h) (Abase + ((s)*2+(h))*5120)
#define BS(s,h) (Bbase + ((s)*2+(h))*5120)

    const int b  = blockIdx.z;
    const int M0 = blockIdx.y * 128;
    const int N0 = blockIdx.x * 128;
    const int tid  = threadIdx.x;
    const int lane = tid & 31;
    const int warp = tid >> 5;
    const int wm = warp >> 2;     // 0..1
    const int wn = warp & 3;      // 0..3

    const __nv_bfloat16* Abh = Ah + (size_t)b*aBatch + (size_t)M0*aStride;
    const __nv_bfloat16* Abl = Al + (size_t)b*aBatch + (size_t)M0*aStride;
    const __nv_bfloat16* Bbh = Bh + (size_t)b*bBatch + (size_t)N0*bStride;
    const __nv_bfloat16* Bbl = Bl + (size_t)b*bBatch + (size_t)N0*bStride;

    float acc[4][4][4];
#pragma unroll
    for (int i = 0; i < 4; i++)
#pragma unroll
        for (int j = 0; j < 4; j++)
#pragma unroll
            for (int r = 0; r < 4; r++) acc[i][j][r] = 0.f;

    const int T = Ktot >> 5;   // K chunks of 32

    // prologue: load stage 0
    {
#pragma unroll
        for (int it = 0; it < 2; it++) {
            int t = tid + it*256;
            int row = t >> 2, seg = (t & 3) * 8;
            cpasync16(AS(0,0)+row*40+seg, Abh + (size_t)row*aStride + seg);
            cpasync16(AS(0,1)+row*40+seg, Abl + (size_t)row*aStride + seg);
            cpasync16(BS(0,0)+row*40+seg, Bbh + (size_t)row*bStride + seg);
            cpasync16(BS(0,1)+row*40+seg, Bbl + (size_t)row*bStride + seg);
        }
        cp_commit();
    }

    for (int t = 0; t < T; t++) {
        const int cur = t & 1;
        if (t + 1 < T) {
            const int nxt = cur ^ 1;
            const int k0 = (t + 1) << 5;
#pragma unroll
            for (int it = 0; it < 2; it++) {
                int e = tid + it*256;
                int row = e >> 2, seg = (e & 3) * 8;
                cpasync16(AS(nxt,0)+row*40+seg, Abh + (size_t)row*aStride + k0 + seg);
                cpasync16(AS(nxt,1)+row*40+seg, Abl + (size_t)row*aStride + k0 + seg);
                cpasync16(BS(nxt,0)+row*40+seg, Bbh + (size_t)row*bStride + k0 + seg);
                cpasync16(BS(nxt,1)+row*40+seg, Bbl + (size_t)row*bStride + k0 + seg);
            }
            cp_commit();
            asm volatile("cp.async.wait_group 1;\n" ::);
        } else {
            asm volatile("cp.async.wait_group 0;\n" ::);
        }
        __syncthreads();

#pragma unroll
        for (int kk = 0; kk < 32; kk += 16) {
            // load all B fragments first (hi+lo): 16 regs
            uint32_t Bf[2][4][2];
#pragma unroll
            for (int p = 0; p < 2; p++) {
                int r = wn*32 + p*16 + ((lane >> 4) << 3) + (lane & 7);
                int c = kk + (((lane >> 3) & 1) << 3);
                uint32_t r0, r1, r2, r3;
                ldsm4(r0, r1, r2, r3, BS(cur,0)+r*40+c);
                Bf[0][2*p][0] = r0; Bf[0][2*p][1] = r1;
                Bf[0][2*p+1][0] = r2; Bf[0][2*p+1][1] = r3;
                ldsm4(r0, r1, r2, r3, BS(cur,1)+r*40+c);
                Bf[1][2*p][0] = r0; Bf[1][2*p][1] = r1;
                Bf[1][2*p+1][0] = r2; Bf[1][2*p+1][1] = r3;
            }
            // stream A per mi: only 8 A regs live at a time
#pragma unroll
            for (int mi = 0; mi < 4; mi++) {
                int r = wm*64 + mi*16 + (lane & 15);
                int c = kk + ((lane >> 4) << 3);
                uint32_t Ahf[4], Alf[4];
                ldsm4(Ahf[0], Ahf[1], Ahf[2], Ahf[3], AS(cur,0)+r*40+c);
                ldsm4(Alf[0], Alf[1], Alf[2], Alf[3], AS(cur,1)+r*40+c);
#pragma unroll
                for (int ni = 0; ni < 4; ni++) {
                    mma16816(acc[mi][ni], Ahf, Bf[0][ni]);
                    mma16816(acc[mi][ni], Ahf, Bf[1][ni]);
                    mma16816(acc[mi][ni], Alf, Bf[0][ni]);
                }
            }
        }
        __syncthreads();
    }

    const int g = lane >> 2, tg2 = (lane & 3) * 2;
    if (Df) {
        float* Db = Df + (size_t)b*dBatch;
#pragma unroll
        for (int mi = 0; mi < 4; mi++)
#pragma unroll
            for (int ni = 0; ni < 4; ni++) {
                int row = M0 + wm*64 + mi*16 + g;
                int col = N0 + wn*32 + ni*8 + tg2;
                float b0 = bias ? bias[col] : 0.f;
                float b1 = bias ? bias[col+1] : 0.f;
                *(float2*)&Db[(size_t)row*dStride + col] =
                    make_float2(acc[mi][ni][0]+b0, acc[mi][ni][1]+b1);
                *(float2*)&Db[(size_t)(row+8)*dStride + col] =
                    make_float2(acc[mi][ni][2]+b0, acc[mi][ni][3]+b1);
            }
    } else {
        __nv_bfloat16* Dbh = Dh + (size_t)b*dBatch;
        __nv_bfloat16* Dbl = Dl + (size_t)b*dBatch;
#pragma unroll
        for (int mi = 0; mi < 4; mi++)
#pragma unroll
            for (int ni = 0; ni < 4; ni++) {
                int row = M0 + wm*64 + mi*16 + g;
                int col = N0 + wn*32 + ni*8 + tg2;
                __nv_bfloat16 h0,l0,h1,l1;
                __nv_bfloat162 hp, lp;
                split_bf16(acc[mi][ni][0], h0, l0);
                split_bf16(acc[mi][ni][1], h1, l1);
                hp.x = h0; hp.y = h1; lp.x = l0; lp.y = l1;
                *(__nv_bfloat162*)&Dbh[(size_t)row*dStride + col] = hp;
                *(__nv_bfloat162*)&Dbl[(size_t)row*dStride + col] = lp;
                split_bf16(acc[mi][ni][2], h0, l0);
                split_bf16(acc[mi][ni][3], h1, l1);
                hp.x = h0; hp.y = h1; lp.x = l0; lp.y = l1;
                *(__nv_bfloat162*)&Dbh[(size_t)(row+8)*dStride + col] = hp;
                *(__nv_bfloat162*)&Dbl[(size_t)(row+8)*dStride + col] = lp;
            }
    }
#undef AS
#undef BS
}

// =========================================================================
// merged weight split: 4 weights in one launch (blockIdx.y selects)
// =========================================================================
__global__ __launch_bounds__(256) void wsplit_all(
    const float* __restrict__ Wk, const float* __restrict__ Wq,
    const float* __restrict__ Wv, const float* __restrict__ W2)
{
    const int sel = blockIdx.y;
    const float* W = sel == 0 ? Wk : sel == 1 ? Wq : sel == 2 ? Wv : W2;
    __nv_bfloat16* h = sel == 0 ? g_wkh : sel == 1 ? g_wqh : sel == 2 ? g_wvh : g_w2h;
    __nv_bfloat16* l = sel == 0 ? g_wkl : sel == 1 ? g_wql : sel == 2 ? g_wvl : g_w2l;
    int i = blockIdx.x * 256 + threadIdx.x;
    split_bf16(W[i], h[i], l[i]);
}

// =========================================================================
// x transpose + split: x [b][c][n] fp32 -> xT hi/lo [b][n][c]
// =========================================================================
__global__ __launch_bounds__(256) void xsplit_kernel(const float* __restrict__ x)
{
    __shared__ float Tm[32][33];
    const int b = blockIdx.z;
    const float* src = x + (size_t)b*CC*NN;
    __nv_bfloat16* dh = g_xth + (size_t)b*NN*CC;
    __nv_bfloat16* dl = g_xtl + (size_t)b*NN*CC;
    const int n0 = blockIdx.x * 32, c0 = blockIdx.y * 32;
    const int tx = threadIdx.x & 31, ty = threadIdx.x >> 5;

#pragma unroll
    for (int j = 0; j < 4; j++)
        Tm[ty + j*8][tx] = src[(size_t)(c0 + ty + j*8)*NN + n0 + tx];
    __syncthreads();
#pragma unroll
    for (int j = 0; j < 4; j++) {
        float v = Tm[tx][ty + j*8];
        int n = n0 + ty + j*8;
        __nv_bfloat16 h, l;
        split_bf16(v, h, l);
        dh[(size_t)n*CC + c0 + tx] = h;
        dl[(size_t)n*CC + c0 + tx] = l;
    }
}

// =========================================================================
// softmax over m of g_s; writes split bf16 probs
// =========================================================================
__global__ __launch_bounds__(256) void softmax_kernel()
{
    const int b = blockIdx.y, n = blockIdx.x;
    const float* row = g_s + ((size_t)b*NN + n) * NN;
    __nv_bfloat16* ph = g_ph + ((size_t)b*NN + n) * NN;
    __nv_bfloat16* pl = g_pl + ((size_t)b*NN + n) * NN;
    const int tid = threadIdx.x;
    float v[9];
    float mx = -1e30f;
#pragma unroll
    for (int i = 0; i < 9; i++) { v[i] = row[tid + i*256]; mx = fmaxf(mx, v[i]); }

    __shared__ float red[8];
#pragma unroll
    for (int off = 16; off; off >>= 1) mx = fmaxf(mx, __shfl_xor_sync(0xffffffffu, mx, off));
    if ((tid & 31) == 0) red[tid >> 5] = mx;
    __syncthreads();
    float gmx = red[0];
#pragma unroll
    for (int i = 1; i < 8; i++) gmx = fmaxf(gmx, red[i]);

    float s = 0.f;
#pragma unroll
    for (int i = 0; i < 9; i++) { v[i] = __expf(v[i] - gmx); s += v[i]; }
    __syncthreads();
#pragma unroll
    for (int off = 16; off; off >>= 1) s += __shfl_xor_sync(0xffffffffu, s, off);
    if ((tid & 31) == 0) red[tid >> 5] = s;
    __syncthreads();
    float tot = 0.f;
#pragma unroll
    for (int i = 0; i < 8; i++) tot += red[i];
    float inv = 1.0f / tot;
#pragma unroll
    for (int i = 0; i < 9; i++) {
        float p = v[i] * inv;
        __nv_bfloat16 h, l;
        split_bf16(p, h, l);
        ph[tid + i*256] = h;
        pl[tid + i*256] = l;
    }
}

// =========================================================================
// BatchNorm stats over y [b][n][o], two-phase.
// Phase 1: grid (CC/32, 48) — each block reduces a 48-row slab over all batches.
// Phase 2: one block reduces 48 partials per channel.
// =========================================================================
__global__ __launch_bounds__(256) void bnstats_part()
{
    const int tx = threadIdx.x & 31, ty = threadIdx.x >> 5;
    const int o = blockIdx.x * 32 + tx;
    const int slab = blockIdx.y;
    const int nbase = slab * 48;
    float s1 = 0.f, s2 = 0.f;
#pragma unroll
    for (int b = 0; b < BB; b++) {
        const float* yb = g_y + (size_t)b*NN*CC;
#pragma unroll
        for (int j = 0; j < 6; j++) {
            float v = yb[(size_t)(nbase + ty + j*8)*CC + o];
            s1 += v; s2 += v*v;
        }
    }
    __shared__ float r1[8][33], r2[8][33];
    r1[ty][tx] = s1; r2[ty][tx] = s2;
    __syncthreads();
    if (ty == 0) {
        float S1 = s1, S2 = s2;
#pragma unroll
        for (int i = 1; i < 8; i++) { S1 += r1[i][tx]; S2 += r2[i][tx]; }
        g_p1[slab][o] = S1;
        g_p2[slab][o] = S2;
    }
}

__global__ __launch_bounds__(256) void bnstats_fin()
{
    const int o = threadIdx.x;
    float S1 = 0.f, S2 = 0.f;
#pragma unroll
    for (int s = 0; s < 48; s++) { S1 += g_p1[s][o]; S2 += g_p2[s][o]; }
    const float invM = 1.0f / (float)(BB*NN);
    float mean = S1 * invM;
    float var  = S2 * invM - mean*mean;
    g_mean[o] = mean;
    g_rstd[o] = rsqrtf(var + 1e-5f);
}

// =========================================================================
// normalize + affine + transpose: y [b][n][o] -> out [b][o][n]
// =========================================================================
__global__ __launch_bounds__(256) void bnorm_kernel(
    const float* __restrict__ gamma, const float* __restrict__ beta,
    float* __restrict__ out)
{
    __shared__ float Tm[32][33];
    const int b = blockIdx.z;
    const int n0 = blockIdx.x * 32, o0 = blockIdx.y * 32;
    const int tx = threadIdx.x & 31, ty = threadIdx.x >> 5;
    const float* yb = g_y + (size_t)b*NN*CC;
#pragma unroll
    for (int j = 0; j < 4; j++)
        Tm[ty + j*8][tx] = yb[(size_t)(n0 + ty + j*8)*CC + o0 + tx];
    __syncthreads();
#pragma unroll
    for (int j = 0; j < 4; j++) {
        int o = o0 + ty + j*8;
        float sc = g_rstd[o] * gamma[o];
        float mb = g_mean[o];
        out[((size_t)b*CC + o)*NN + n0 + tx] = (Tm[tx][ty + j*8] - mb) * sc + beta[o];
    }
}

// =========================================================================
extern "C" void kernel_launch(void* const* d_in, const int* in_sizes, int n_in,
                              void* d_out, int out_size)
{
    (void)in_sizes; (void)n_in; (void)out_size;
    const float* x     = (const float*)d_in[0];
    const float* Wk    = (const float*)d_in[1];
    const float* Wq    = (const float*)d_in[2];
    const float* Wv    = (const float*)d_in[3];
    const float* W2    = (const float*)d_in[4];
    const float* b2    = (const float*)d_in[5];
    const float* gamma = (const float*)d_in[6];
    const float* beta  = (const float*)d_in[7];
    float* out = (float*)d_out;

    float *ps, *py;
    __nv_bfloat16 *pxth,*pxtl,*pkth,*pktl,*pqth,*pqtl,*pvh,*pvl,*path,*patl,*pph,*ppl;
    __nv_bfloat16 *pwkh,*pwkl,*pwqh,*pwql,*pwvh,*pwvl,*pw2h,*pw2l;
    cudaGetSymbolAddress((void**)&ps,   g_s);
    cudaGetSymbolAddress((void**)&py,   g_y);
    cudaGetSymbolAddress((void**)&pxth, g_xth); cudaGetSymbolAddress((void**)&pxtl, g_xtl);
    cudaGetSymbolAddress((void**)&pkth, g_kth); cudaGetSymbolAddress((void**)&pktl, g_ktl);
    cudaGetSymbolAddress((void**)&pqth, g_qth); cudaGetSymbolAddress((void**)&pqtl, g_qtl);
    cudaGetSymbolAddress((void**)&pvh,  g_vh);  cudaGetSymbolAddress((void**)&pvl,  g_vl);
    cudaGetSymbolAddress((void**)&path, g_ath); cudaGetSymbolAddress((void**)&patl, g_atl);
    cudaGetSymbolAddress((void**)&pph,  g_ph);  cudaGetSymbolAddress((void**)&ppl,  g_pl);
    cudaGetSymbolAddress((void**)&pwkh, g_wkh); cudaGetSymbolAddress((void**)&pwkl, g_wkl);
    cudaGetSymbolAddress((void**)&pwqh, g_wqh); cudaGetSymbolAddress((void**)&pwql, g_wql);
    cudaGetSymbolAddress((void**)&pwvh, g_wvh); cudaGetSymbolAddress((void**)&pwvl, g_wvl);
    cudaGetSymbolAddress((void**)&pw2h, g_w2h); cudaGetSymbolAddress((void**)&pw2l, g_w2l);

    const int SMEM = 2*2*128*40*2*2;   // 81920 bytes
    cudaFuncSetAttribute(mma_split_gemm, cudaFuncAttributeMaxDynamicSharedMemorySize, SMEM);

    dim3 blk(256);

    wsplit_all<<<dim3(CC*CC/256, 4), blk>>>(Wk, Wq, Wv, W2);

    xsplit_kernel<<<dim3(NN/32, CC/32, BB), blk>>>(x);

    // kT[b][n][o] = sum_c xT[n][c] * Wk[o][c]   (split out)
    mma_split_gemm<<<dim3(CC/128, NN/128, BB), blk, SMEM>>>(
        pxth, pxtl, (size_t)NN*CC, CC,  pwkh, pwkl, 0, CC,
        nullptr, pkth, pktl, nullptr, (size_t)NN*CC, CC, CC);
    // qT
    mma_split_gemm<<<dim3(CC/128, NN/128, BB), blk, SMEM>>>(
        pxth, pxtl, (size_t)NN*CC, CC,  pwqh, pwql, 0, CC,
        nullptr, pqth, pqtl, nullptr, (size_t)NN*CC, CC, CC);
    // v[b][c][m] = sum_c' Wv[c][c'] * xT[m][c']   (split out)
    mma_split_gemm<<<dim3(NN/128, CC/128, BB), blk, SMEM>>>(
        pwvh, pwvl, 0, CC,  pxth, pxtl, (size_t)NN*CC, CC,
        nullptr, pvh, pvl, nullptr, (size_t)CC*NN, NN, CC);

    // scores[b][n][m] = sum_c kT[n][c]*qT[m][c]  (fp32 out)
    mma_split_gemm<<<dim3(NN/128, NN/128, BB), blk, SMEM>>>(
        pkth, pktl, (size_t)NN*CC, CC,  pqth, pqtl, (size_t)NN*CC, CC,
        ps, nullptr, nullptr, nullptr, (size_t)NN*NN, NN, CC);

    softmax_kernel<<<dim3(NN, BB), blk>>>();

    // attnT[b][n][c] = sum_m P[n][m]*v[c][m]  (split out)
    mma_split_gemm<<<dim3(CC/128, NN/128, BB), blk, SMEM>>>(
        pph, ppl, (size_t)NN*NN, NN,  pvh, pvl, (size_t)CC*NN, NN,
        nullptr, path, patl, nullptr, (size_t)NN*CC, CC, NN);

    // y[b][n][o] = sum_c attnT[n][c]*W2[o][c] + b2[o]  (fp32 out)
    mma_split_gemm<<<dim3(CC/128, NN/128, BB), blk, SMEM>>>(
        path, patl, (size_t)NN*CC, CC,  pw2h, pw2l, 0, CC,
        py, nullptr, nullptr, b2, (size_t)NN*CC, CC, CC);

    bnstats_part<<<dim3(CC/32, 48), blk>>>();
    bnstats_fin<<<1, CC>>>();

    bnorm_kernel<<<dim3(NN/32, CC/32, BB), blk>>>(gamma, beta, out);
}

// round 8
// speedup vs baseline: 2.7698x; 1.0281x over previous
#include <cuda_runtime.h>
#include <cuda_bf16.h>
#include <cstddef>
#include <cstdint>

#define BB 8
#define CC 256
#define NN 2304            // 48*48

// ---------------- scratch (static device memory: allowed) ----------------
__device__ __align__(16) float g_s[(size_t)BB*NN*NN];   // 170 MB scores
__device__ __align__(16) float g_y[(size_t)BB*NN*CC];   // y in [b][n][o]
__device__ float g_mean[CC];
__device__ float g_rstd[CC];
__device__ float g_p1[48][CC];
__device__ float g_p2[48][CC];

// split bf16 operands
__device__ __align__(16) __nv_bfloat16 g_xth[(size_t)BB*NN*CC],  g_xtl[(size_t)BB*NN*CC];  // xT [b][n][c]
__device__ __align__(16) __nv_bfloat16 g_kqth[(size_t)BB*NN*512], g_kqtl[(size_t)BB*NN*512]; // [b][n][k|q]
__device__ __align__(16) __nv_bfloat16 g_vh [(size_t)BB*CC*NN],  g_vl [(size_t)BB*CC*NN];  // v  [b][c][m]
__device__ __align__(16) __nv_bfloat16 g_ath[(size_t)BB*NN*CC],  g_atl[(size_t)BB*NN*CC];  // attnT [b][n][c]
__device__ __align__(16) __nv_bfloat16 g_ph [(size_t)BB*NN*NN],  g_pl [(size_t)BB*NN*NN];  // P [b][n][m]
__device__ __align__(16) __nv_bfloat16 g_wkqh[2*CC*CC], g_wkql[2*CC*CC];  // [Wk;Wq]
__device__ __align__(16) __nv_bfloat16 g_wvh[CC*CC], g_wvl[CC*CC];
__device__ __align__(16) __nv_bfloat16 g_w2h[CC*CC], g_w2l[CC*CC];

// ---------------- helpers ----------------
__device__ __forceinline__ void split_bf16(float f, __nv_bfloat16& h, __nv_bfloat16& l) {
    h = __float2bfloat16(f);
    l = __float2bfloat16(f - __bfloat162float(h));
}

__device__ __forceinline__ void ldsm4(uint32_t& r0, uint32_t& r1, uint32_t& r2, uint32_t& r3,
                                      const void* p) {
    uint32_t a = (uint32_t)__cvta_generic_to_shared(p);
    asm volatile("ldmatrix.sync.aligned.m8n8.x4.shared.b16 {%0,%1,%2,%3}, [%4];\n"
                 : "=r"(r0), "=r"(r1), "=r"(r2), "=r"(r3) : "r"(a));
}

__device__ __forceinline__ void mma16816(float* c, const uint32_t* a, const uint32_t* b) {
    asm volatile("mma.sync.aligned.m16n8k16.row.col.f32.bf16.bf16.f32 "
                 "{%0,%1,%2,%3}, {%4,%5,%6,%7}, {%8,%9}, {%0,%1,%2,%3};\n"
                 : "+f"(c[0]), "+f"(c[1]), "+f"(c[2]), "+f"(c[3])
                 : "r"(a[0]), "r"(a[1]), "r"(a[2]), "r"(a[3]), "r"(b[0]), "r"(b[1]));
}

__device__ __forceinline__ void cpasync16(void* s, const void* g) {
    uint32_t a = (uint32_t)__cvta_generic_to_shared(s);
    asm volatile("cp.async.cg.shared.global [%0], [%1], 16;\n" :: "r"(a), "l"(g));
}
__device__ __forceinline__ void cp_commit() { asm volatile("cp.async.commit_group;\n" ::); }

// =========================================================================
// split-bf16 tensor-core GEMM: D[b][M0+r][N0+c] = sum_k A[r][k]*B[c][k]
// 3 MMAs per fragment (hi*hi + hi*lo + lo*hi).
// block 128x128, 8 warps (2x4), warp tile 64x32, K-chunk 32, 2-stage cp.async,
// ONE __syncthreads per chunk. __launch_bounds__(256,2) -> 2 CTAs/SM.
// =========================================================================
__global__ __launch_bounds__(256, 2) void mma_split_gemm(
    const __nv_bfloat16* __restrict__ Ah, const __nv_bfloat16* __restrict__ Al,
    size_t aBatch, int aStride,
    const __nv_bfloat16* __restrict__ Bh, const __nv_bfloat16* __restrict__ Bl,
    size_t bBatch, int bStride,
    float* __restrict__ Df,
    __nv_bfloat16* __restrict__ Dh, __nv_bfloat16* __restrict__ Dl,
    const float* __restrict__ bias,
    size_t dBatch, int dStride, int Ktot)
{
    extern __shared__ __align__(16) __nv_bfloat16 smem[];
    __nv_bfloat16* Abase = smem;                   // [2 stage][2 hi/lo][128*40]
    __nv_bfloat16* Bbase = smem + 2*2*128*40;
#define AS(s,h) (Abase + ((s)*2+(h))*5120)
#define BS(s,h) (Bbase + ((s)*2+(h))*5120)

    const int b  = blockIdx.z;
    const int M0 = blockIdx.y * 128;
    const int N0 = blockIdx.x * 128;
    const int tid  = threadIdx.x;
    const int lane = tid & 31;
    const int warp = tid >> 5;
    const int wm = warp >> 2;     // 0..1
    const int wn = warp & 3;      // 0..3

    const __nv_bfloat16* Abh = Ah + (size_t)b*aBatch + (size_t)M0*aStride;
    const __nv_bfloat16* Abl = Al + (size_t)b*aBatch + (size_t)M0*aStride;
    const __nv_bfloat16* Bbh = Bh + (size_t)b*bBatch + (size_t)N0*bStride;
    const __nv_bfloat16* Bbl = Bl + (size_t)b*bBatch + (size_t)N0*bStride;

    float acc[4][4][4];
#pragma unroll
    for (int i = 0; i < 4; i++)
#pragma unroll
        for (int j = 0; j < 4; j++)
#pragma unroll
            for (int r = 0; r < 4; r++) acc[i][j][r] = 0.f;

    const int T = Ktot >> 5;   // K chunks of 32

    // prologue: load stage 0
    {
#pragma unroll
        for (int it = 0; it < 2; it++) {
            int t = tid + it*256;
            int row = t >> 2, seg = (t & 3) * 8;
            cpasync16(AS(0,0)+row*40+seg, Abh + (size_t)row*aStride + seg);
            cpasync16(AS(0,1)+row*40+seg, Abl + (size_t)row*aStride + seg);
            cpasync16(BS(0,0)+row*40+seg, Bbh + (size_t)row*bStride + seg);
            cpasync16(BS(0,1)+row*40+seg, Bbl + (size_t)row*bStride + seg);
        }
        cp_commit();
    }

    for (int t = 0; t < T; t++) {
        const int cur = t & 1;
        asm volatile("cp.async.wait_group 0;\n" ::);
        __syncthreads();

        if (t + 1 < T) {
            const int nxt = cur ^ 1;
            const int k0 = (t + 1) << 5;
#pragma unroll
            for (int it = 0; it < 2; it++) {
                int e = tid + it*256;
                int row = e >> 2, seg = (e & 3) * 8;
                cpasync16(AS(nxt,0)+row*40+seg, Abh + (size_t)row*aStride + k0 + seg);
                cpasync16(AS(nxt,1)+row*40+seg, Abl + (size_t)row*aStride + k0 + seg);
                cpasync16(BS(nxt,0)+row*40+seg, Bbh + (size_t)row*bStride + k0 + seg);
                cpasync16(BS(nxt,1)+row*40+seg, Bbl + (size_t)row*bStride + k0 + seg);
            }
            cp_commit();
        }

#pragma unroll
        for (int kk = 0; kk < 32; kk += 16) {
            uint32_t Bf[2][4][2];
#pragma unroll
            for (int p = 0; p < 2; p++) {
                int r = wn*32 + p*16 + ((lane >> 4) << 3) + (lane & 7);
                int c = kk + (((lane >> 3) & 1) << 3);
                uint32_t r0, r1, r2, r3;
                ldsm4(r0, r1, r2, r3, BS(cur,0)+r*40+c);
                Bf[0][2*p][0] = r0; Bf[0][2*p][1] = r1;
                Bf[0][2*p+1][0] = r2; Bf[0][2*p+1][1] = r3;
                ldsm4(r0, r1, r2, r3, BS(cur,1)+r*40+c);
                Bf[1][2*p][0] = r0; Bf[1][2*p][1] = r1;
                Bf[1][2*p+1][0] = r2; Bf[1][2*p+1][1] = r3;
            }
#pragma unroll
            for (int mi = 0; mi < 4; mi++) {
                int r = wm*64 + mi*16 + (lane & 15);
                int c = kk + ((lane >> 4) << 3);
                uint32_t Ahf[4], Alf[4];
                ldsm4(Ahf[0], Ahf[1], Ahf[2], Ahf[3], AS(cur,0)+r*40+c);
                ldsm4(Alf[0], Alf[1], Alf[2], Alf[3], AS(cur,1)+r*40+c);
#pragma unroll
                for (int ni = 0; ni < 4; ni++) {
                    mma16816(acc[mi][ni], Ahf, Bf[0][ni]);
                    mma16816(acc[mi][ni], Ahf, Bf[1][ni]);
                    mma16816(acc[mi][ni], Alf, Bf[0][ni]);
                }
            }
        }
    }

    const int g = lane >> 2, tg2 = (lane & 3) * 2;
    if (Df) {
        float* Db = Df + (size_t)b*dBatch;
#pragma unroll
        for (int mi = 0; mi < 4; mi++)
#pragma unroll
            for (int ni = 0; ni < 4; ni++) {
                int row = M0 + wm*64 + mi*16 + g;
                int col = N0 + wn*32 + ni*8 + tg2;
                float b0 = bias ? bias[col] : 0.f;
                float b1 = bias ? bias[col+1] : 0.f;
                *(float2*)&Db[(size_t)row*dStride + col] =
                    make_float2(acc[mi][ni][0]+b0, acc[mi][ni][1]+b1);
                *(float2*)&Db[(size_t)(row+8)*dStride + col] =
                    make_float2(acc[mi][ni][2]+b0, acc[mi][ni][3]+b1);
            }
    } else {
        __nv_bfloat16* Dbh = Dh + (size_t)b*dBatch;
        __nv_bfloat16* Dbl = Dl + (size_t)b*dBatch;
#pragma unroll
        for (int mi = 0; mi < 4; mi++)
#pragma unroll
            for (int ni = 0; ni < 4; ni++) {
                int row = M0 + wm*64 + mi*16 + g;
                int col = N0 + wn*32 + ni*8 + tg2;
                __nv_bfloat16 h0,l0,h1,l1;
                __nv_bfloat162 hp, lp;
                split_bf16(acc[mi][ni][0], h0, l0);
                split_bf16(acc[mi][ni][1], h1, l1);
                hp.x = h0; hp.y = h1; lp.x = l0; lp.y = l1;
                *(__nv_bfloat162*)&Dbh[(size_t)row*dStride + col] = hp;
                *(__nv_bfloat162*)&Dbl[(size_t)row*dStride + col] = lp;
                split_bf16(acc[mi][ni][2], h0, l0);
                split_bf16(acc[mi][ni][3], h1, l1);
                hp.x = h0; hp.y = h1; lp.x = l0; lp.y = l1;
                *(__nv_bfloat162*)&Dbh[(size_t)(row+8)*dStride + col] = hp;
                *(__nv_bfloat162*)&Dbl[(size_t)(row+8)*dStride + col] = lp;
            }
    }
#undef AS
#undef BS
}

// =========================================================================
// merged weight split: Wk,Wq -> concatenated [Wk;Wq]; Wv, W2 separate
// =========================================================================
__global__ __launch_bounds__(256) void wsplit_all(
    const float* __restrict__ Wk, const float* __restrict__ Wq,
    const float* __restrict__ Wv, const float* __restrict__ W2)
{
    const int sel = blockIdx.y;
    const float* W = sel == 0 ? Wk : sel == 1 ? Wq : sel == 2 ? Wv : W2;
    __nv_bfloat16* h = sel == 0 ? g_wkqh : sel == 1 ? (g_wkqh + CC*CC)
                     : sel == 2 ? g_wvh : g_w2h;
    __nv_bfloat16* l = sel == 0 ? g_wkql : sel == 1 ? (g_wkql + CC*CC)
                     : sel == 2 ? g_wvl : g_w2l;
    int i = blockIdx.x * 256 + threadIdx.x;
    split_bf16(W[i], h[i], l[i]);
}

// =========================================================================
// x transpose + split: x [b][c][n] fp32 -> xT hi/lo [b][n][c]
// =========================================================================
__global__ __launch_bounds__(256) void xsplit_kernel(const float* __restrict__ x)
{
    __shared__ float Tm[32][33];
    const int b = blockIdx.z;
    const float* src = x + (size_t)b*CC*NN;
    __nv_bfloat16* dh = g_xth + (size_t)b*NN*CC;
    __nv_bfloat16* dl = g_xtl + (size_t)b*NN*CC;
    const int n0 = blockIdx.x * 32, c0 = blockIdx.y * 32;
    const int tx = threadIdx.x & 31, ty = threadIdx.x >> 5;

#pragma unroll
    for (int j = 0; j < 4; j++)
        Tm[ty + j*8][tx] = src[(size_t)(c0 + ty + j*8)*NN + n0 + tx];
    __syncthreads();
#pragma unroll
    for (int j = 0; j < 4; j++) {
        float v = Tm[tx][ty + j*8];
        int n = n0 + ty + j*8;
        __nv_bfloat16 h, l;
        split_bf16(v, h, l);
        dh[(size_t)n*CC + c0 + tx] = h;
        dl[(size_t)n*CC + c0 + tx] = l;
    }
}

// =========================================================================
// softmax over m of g_s; 288 threads x 8 contiguous elems, vectorized I/O
// =========================================================================
__global__ __launch_bounds__(288) void softmax_kernel()
{
    const int b = blockIdx.y, n = blockIdx.x;
    const float* row = g_s + ((size_t)b*NN + n) * NN;
    __nv_bfloat16* ph = g_ph + ((size_t)b*NN + n) * NN;
    __nv_bfloat16* pl = g_pl + ((size_t)b*NN + n) * NN;
    const int tid = threadIdx.x;
    const int base = tid * 8;

    float4 a0 = *(const float4*)&row[base];
    float4 a1 = *(const float4*)&row[base + 4];
    float v[8] = {a0.x, a0.y, a0.z, a0.w, a1.x, a1.y, a1.z, a1.w};

    float mx = v[0];
#pragma unroll
    for (int i = 1; i < 8; i++) mx = fmaxf(mx, v[i]);

    __shared__ float red[9];
#pragma unroll
    for (int off = 16; off; off >>= 1) mx = fmaxf(mx, __shfl_xor_sync(0xffffffffu, mx, off));
    if ((tid & 31) == 0) red[tid >> 5] = mx;
    __syncthreads();
    float gmx = red[0];
#pragma unroll
    for (int i = 1; i < 9; i++) gmx = fmaxf(gmx, red[i]);

    float s = 0.f;
#pragma unroll
    for (int i = 0; i < 8; i++) { v[i] = __expf(v[i] - gmx); s += v[i]; }
    __syncthreads();
#pragma unroll
    for (int off = 16; off; off >>= 1) s += __shfl_xor_sync(0xffffffffu, s, off);
    if ((tid & 31) == 0) red[tid >> 5] = s;
    __syncthreads();
    float tot = 0.f;
#pragma unroll
    for (int i = 0; i < 9; i++) tot += red[i];
    float inv = 1.0f / tot;

    __align__(16) __nv_bfloat16 h8[8], l8[8];
#pragma unroll
    for (int i = 0; i < 8; i++) split_bf16(v[i] * inv, h8[i], l8[i]);
    *(uint4*)&ph[base] = *(uint4*)h8;
    *(uint4*)&pl[base] = *(uint4*)l8;
}

// =========================================================================
// BatchNorm stats over y [b][n][o], two-phase
// =========================================================================
__global__ __launch_bounds__(256) void bnstats_part()
{
    const int tx = threadIdx.x & 31, ty = threadIdx.x >> 5;
    const int o = blockIdx.x * 32 + tx;
    const int slab = blockIdx.y;
    const int nbase = slab * 48;
    float s1 = 0.f, s2 = 0.f;
#pragma unroll
    for (int b = 0; b < BB; b++) {
        const float* yb = g_y + (size_t)b*NN*CC;
#pragma unroll
        for (int j = 0; j < 6; j++) {
            float v = yb[(size_t)(nbase + ty + j*8)*CC + o];
            s1 += v; s2 += v*v;
        }
    }
    __shared__ float r1[8][33], r2[8][33];
    r1[ty][tx] = s1; r2[ty][tx] = s2;
    __syncthreads();
    if (ty == 0) {
        float S1 = s1, S2 = s2;
#pragma unroll
        for (int i = 1; i < 8; i++) { S1 += r1[i][tx]; S2 += r2[i][tx]; }
        g_p1[slab][o] = S1;
        g_p2[slab][o] = S2;
    }
}

__global__ __launch_bounds__(256) void bnstats_fin()
{
    const int o = threadIdx.x;
    float S1 = 0.f, S2 = 0.f;
#pragma unroll
    for (int s = 0; s < 48; s++) { S1 += g_p1[s][o]; S2 += g_p2[s][o]; }
    const float invM = 1.0f / (float)(BB*NN);
    float mean = S1 * invM;
    float var  = S2 * invM - mean*mean;
    g_mean[o] = mean;
    g_rstd[o] = rsqrtf(var + 1e-5f);
}

// =========================================================================
// normalize + affine + transpose: y [b][n][o] -> out [b][o][n]
// =========================================================================
__global__ __launch_bounds__(256) void bnorm_kernel(
    const float* __restrict__ gamma, const float* __restrict__ beta,
    float* __restrict__ out)
{
    __shared__ float Tm[32][33];
    const int b = blockIdx.z;
    const int n0 = blockIdx.x * 32, o0 = blockIdx.y * 32;
    const int tx = threadIdx.x & 31, ty = threadIdx.x >> 5;
    const float* yb = g_y + (size_t)b*NN*CC;
#pragma unroll
    for (int j = 0; j < 4; j++)
        Tm[ty + j*8][tx] = yb[(size_t)(n0 + ty + j*8)*CC + o0 + tx];
    __syncthreads();
#pragma unroll
    for (int j = 0; j < 4; j++) {
        int o = o0 + ty + j*8;
        float sc = g_rstd[o] * gamma[o];
        float mb = g_mean[o];
        out[((size_t)b*CC + o)*NN + n0 + tx] = (Tm[tx][ty + j*8] - mb) * sc + beta[o];
    }
}

// =========================================================================
extern "C" void kernel_launch(void* const* d_in, const int* in_sizes, int n_in,
                              void* d_out, int out_size)
{
    (void)in_sizes; (void)n_in; (void)out_size;
    const float* x     = (const float*)d_in[0];
    const float* Wk    = (const float*)d_in[1];
    const float* Wq    = (const float*)d_in[2];
    const float* Wv    = (const float*)d_in[3];
    const float* W2    = (const float*)d_in[4];
    const float* b2    = (const float*)d_in[5];
    const float* gamma = (const float*)d_in[6];
    const float* beta  = (const float*)d_in[7];
    float* out = (float*)d_out;

    float *ps, *py;
    __nv_bfloat16 *pxth,*pxtl,*pkqth,*pkqtl,*pvh,*pvl,*path,*patl,*pph,*ppl;
    __nv_bfloat16 *pwkqh,*pwkql,*pwvh,*pwvl,*pw2h,*pw2l;
    cudaGetSymbolAddress((void**)&ps,    g_s);
    cudaGetSymbolAddress((void**)&py,    g_y);
    cudaGetSymbolAddress((void**)&pxth,  g_xth);  cudaGetSymbolAddress((void**)&pxtl,  g_xtl);
    cudaGetSymbolAddress((void**)&pkqth, g_kqth); cudaGetSymbolAddress((void**)&pkqtl, g_kqtl);
    cudaGetSymbolAddress((void**)&pvh,   g_vh);   cudaGetSymbolAddress((void**)&pvl,   g_vl);
    cudaGetSymbolAddress((void**)&path,  g_ath);  cudaGetSymbolAddress((void**)&patl,  g_atl);
    cudaGetSymbolAddress((void**)&pph,   g_ph);   cudaGetSymbolAddress((void**)&ppl,   g_pl);
    cudaGetSymbolAddress((void**)&pwkqh, g_wkqh); cudaGetSymbolAddress((void**)&pwkql, g_wkql);
    cudaGetSymbolAddress((void**)&pwvh,  g_wvh);  cudaGetSymbolAddress((void**)&pwvl,  g_wvl);
    cudaGetSymbolAddress((void**)&pw2h,  g_w2h);  cudaGetSymbolAddress((void**)&pw2l,  g_w2l);

    const int SMEM = 2*2*128*40*2*2;   // 81920 bytes
    cudaFuncSetAttribute(mma_split_gemm, cudaFuncAttributeMaxDynamicSharedMemorySize, SMEM);

    dim3 blk(256);

    wsplit_all<<<dim3(CC*CC/256, 4), blk>>>(Wk, Wq, Wv, W2);

    xsplit_kernel<<<dim3(NN/32, CC/32, BB), blk>>>(x);

    // kqT[b][n][o] = sum_c xT[n][c] * Wkq[o][c], o in [0,512)  (split out)
    mma_split_gemm<<<dim3(512/128, NN/128, BB), blk, SMEM>>>(
        pxth, pxtl, (size_t)NN*CC, CC,  pwkqh, pwkql, 0, CC,
        nullptr, pkqth, pkqtl, nullptr, (size_t)NN*512, 512, CC);

    // v[b][c][m] = sum_c' Wv[c][c'] * xT[m][c']   (split out)
    mma_split_gemm<<<dim3(NN/128, CC/128, BB), blk, SMEM>>>(
        pwvh, pwvl, 0, CC,  pxth, pxtl, (size_t)NN*CC, CC,
        nullptr, pvh, pvl, nullptr, (size_t)CC*NN, NN, CC);

    // scores[b][n][m] = sum_c kT[n][c]*qT[m][c]  (fp32 out)
    // kT = kqT cols [0,256), qT = kqT cols [256,512)
    mma_split_gemm<<<dim3(NN/128, NN/128, BB), blk, SMEM>>>(
        pkqth, pkqtl, (size_t)NN*512, 512,
        pkqth + CC, pkqtl + CC, (size_t)NN*512, 512,
        ps, nullptr, nullptr, nullptr, (size_t)NN*NN, NN, CC);

    softmax_kernel<<<dim3(NN, BB), 288>>>();

    // attnT[b][n][c] = sum_m P[n][m]*v[c][m]  (split out)
    mma_split_gemm<<<dim3(CC/128, NN/128, BB), blk, SMEM>>>(
        pph, ppl, (size_t)NN*NN, NN,  pvh, pvl, (size_t)CC*NN, NN,
        nullptr, path, patl, nullptr, (size_t)NN*CC, CC, NN);

    // y[b][n][o] = sum_c attnT[n][c]*W2[o][c] + b2[o]  (fp32 out)
    mma_split_gemm<<<dim3(CC/128, NN/128, BB), blk, SMEM>>>(
        path, patl, (size_t)NN*CC, CC,  pw2h, pw2l, 0, CC,
        py, nullptr, nullptr, b2, (size_t)NN*CC, CC, CC);

    bnstats_part<<<dim3(CC/32, 48), blk>>>();
    bnstats_fin<<<1, CC>>>();

    bnorm_kernel<<<dim3(NN/32, CC/32, BB), blk>>>(gamma, beta, out);
}

// round 9
// speedup vs baseline: 2.7763x; 1.0023x over previous
#include <cuda_runtime.h>
#include <cuda_bf16.h>
#include <cstddef>
#include <cstdint>

#define BB 8
#define CC 256
#define NN 2304            // 48*48

// ---------------- scratch (static device memory: allowed) ----------------
__device__ __align__(16) float g_s[(size_t)BB*NN*NN];   // 170 MB scores
__device__ __align__(16) float g_y[(size_t)BB*NN*CC];   // y in [b][n][o]
__device__ float g_mean[CC];
__device__ float g_rstd[CC];
__device__ float g_p1[48][CC];
__device__ float g_p2[48][CC];

// split bf16 operands
__device__ __align__(16) __nv_bfloat16 g_xth[(size_t)BB*NN*CC],  g_xtl[(size_t)BB*NN*CC];  // xT [b][n][c]
__device__ __align__(16) __nv_bfloat16 g_kqth[(size_t)BB*NN*512], g_kqtl[(size_t)BB*NN*512]; // [b][n][k|q]
__device__ __align__(16) __nv_bfloat16 g_vh [(size_t)BB*CC*NN],  g_vl [(size_t)BB*CC*NN];  // v  [b][c][m]
__device__ __align__(16) __nv_bfloat16 g_ath[(size_t)BB*NN*CC],  g_atl[(size_t)BB*NN*CC];  // attnT [b][n][c]
__device__ __align__(16) __nv_bfloat16 g_ph [(size_t)BB*NN*NN],  g_pl [(size_t)BB*NN*NN];  // P [b][n][m]
__device__ __align__(16) __nv_bfloat16 g_wkqh[2*CC*CC], g_wkql[2*CC*CC];  // [Wk;Wq]
__device__ __align__(16) __nv_bfloat16 g_wvh[CC*CC], g_wvl[CC*CC];
__device__ __align__(16) __nv_bfloat16 g_w2h[CC*CC], g_w2l[CC*CC];

// ---------------- helpers ----------------
__device__ __forceinline__ void split_bf16(float f, __nv_bfloat16& h, __nv_bfloat16& l) {
    h = __float2bfloat16(f);
    l = __float2bfloat16(f - __bfloat162float(h));
}

__device__ __forceinline__ void ldsm4(uint32_t& r0, uint32_t& r1, uint32_t& r2, uint32_t& r3,
                                      const void* p) {
    uint32_t a = (uint32_t)__cvta_generic_to_shared(p);
    asm volatile("ldmatrix.sync.aligned.m8n8.x4.shared.b16 {%0,%1,%2,%3}, [%4];\n"
                 : "=r"(r0), "=r"(r1), "=r"(r2), "=r"(r3) : "r"(a));
}

__device__ __forceinline__ void mma16816(float* c, const uint32_t* a, const uint32_t* b) {
    asm volatile("mma.sync.aligned.m16n8k16.row.col.f32.bf16.bf16.f32 "
                 "{%0,%1,%2,%3}, {%4,%5,%6,%7}, {%8,%9}, {%0,%1,%2,%3};\n"
                 : "+f"(c[0]), "+f"(c[1]), "+f"(c[2]), "+f"(c[3])
                 : "r"(a[0]), "r"(a[1]), "r"(a[2]), "r"(a[3]), "r"(b[0]), "r"(b[1]));
}

__device__ __forceinline__ void cpasync16(void* s, const void* g) {
    uint32_t a = (uint32_t)__cvta_generic_to_shared(s);
    asm volatile("cp.async.cg.shared.global [%0], [%1], 16;\n" :: "r"(a), "l"(g));
}
__device__ __forceinline__ void cp_commit() { asm volatile("cp.async.commit_group;\n" ::); }

// =========================================================================
// split-bf16 tensor-core GEMM: D[b][M0+r][N0+c] = sum_k A[r][k]*B[c][k]
// 3 MMAs per fragment (hi*hi + hi*lo + lo*hi), TERM-MAJOR order so each
// accumulator's 3 MMAs are 4 issues apart (breaks the latency chain).
// block 128x128, 8 warps (2x4), warp tile 64x32, K-chunk 32, 2-stage cp.async,
// one __syncthreads per chunk. __launch_bounds__(256,2) -> 2 CTAs/SM.
// =========================================================================
__global__ __launch_bounds__(256, 2) void mma_split_gemm(
    const __nv_bfloat16* __restrict__ Ah, const __nv_bfloat16* __restrict__ Al,
    size_t aBatch, int aStride,
    const __nv_bfloat16* __restrict__ Bh, const __nv_bfloat16* __restrict__ Bl,
    size_t bBatch, int bStride,
    float* __restrict__ Df,
    __nv_bfloat16* __restrict__ Dh, __nv_bfloat16* __restrict__ Dl,
    const float* __restrict__ bias,
    size_t dBatch, int dStride, int Ktot)
{
    extern __shared__ __align__(16) __nv_bfloat16 smem[];
    __nv_bfloat16* Abase = smem;                   // [2 stage][2 hi/lo][128*40]
    __nv_bfloat16* Bbase = smem + 2*2*128*40;
#define AS(s,h) (Abase + ((s)*2+(h))*5120)
#define BS(s,h) (Bbase + ((s)*2+(h))*5120)

    const int b  = blockIdx.z;
    const int M0 = blockIdx.y * 128;
    const int N0 = blockIdx.x * 128;
    const int tid  = threadIdx.x;
    const int lane = tid & 31;
    const int warp = tid >> 5;
    const int wm = warp >> 2;     // 0..1
    const int wn = warp & 3;      // 0..3

    const __nv_bfloat16* Abh = Ah + (size_t)b*aBatch + (size_t)M0*aStride;
    const __nv_bfloat16* Abl = Al + (size_t)b*aBatch + (size_t)M0*aStride;
    const __nv_bfloat16* Bbh = Bh + (size_t)b*bBatch + (size_t)N0*bStride;
    const __nv_bfloat16* Bbl = Bl + (size_t)b*bBatch + (size_t)N0*bStride;

    float acc[4][4][4];
#pragma unroll
    for (int i = 0; i < 4; i++)
#pragma unroll
        for (int j = 0; j < 4; j++)
#pragma unroll
            for (int r = 0; r < 4; r++) acc[i][j][r] = 0.f;

    const int T = Ktot >> 5;   // K chunks of 32

    // prologue: load stage 0
    {
#pragma unroll
        for (int it = 0; it < 2; it++) {
            int t = tid + it*256;
            int row = t >> 2, seg = (t & 3) * 8;
            cpasync16(AS(0,0)+row*40+seg, Abh + (size_t)row*aStride + seg);
            cpasync16(AS(0,1)+row*40+seg, Abl + (size_t)row*aStride + seg);
            cpasync16(BS(0,0)+row*40+seg, Bbh + (size_t)row*bStride + seg);
            cpasync16(BS(0,1)+row*40+seg, Bbl + (size_t)row*bStride + seg);
        }
        cp_commit();
    }

    for (int t = 0; t < T; t++) {
        const int cur = t & 1;
        asm volatile("cp.async.wait_group 0;\n" ::);
        __syncthreads();

        if (t + 1 < T) {
            const int nxt = cur ^ 1;
            const int k0 = (t + 1) << 5;
#pragma unroll
            for (int it = 0; it < 2; it++) {
                int e = tid + it*256;
                int row = e >> 2, seg = (e & 3) * 8;
                cpasync16(AS(nxt,0)+row*40+seg, Abh + (size_t)row*aStride + k0 + seg);
                cpasync16(AS(nxt,1)+row*40+seg, Abl + (size_t)row*aStride + k0 + seg);
                cpasync16(BS(nxt,0)+row*40+seg, Bbh + (size_t)row*bStride + k0 + seg);
                cpasync16(BS(nxt,1)+row*40+seg, Bbl + (size_t)row*bStride + k0 + seg);
            }
            cp_commit();
        }

#pragma unroll
        for (int kk = 0; kk < 32; kk += 16) {
            uint32_t Bf[2][4][2];
#pragma unroll
            for (int p = 0; p < 2; p++) {
                int r = wn*32 + p*16 + ((lane >> 4) << 3) + (lane & 7);
                int c = kk + (((lane >> 3) & 1) << 3);
                uint32_t r0, r1, r2, r3;
                ldsm4(r0, r1, r2, r3, BS(cur,0)+r*40+c);
                Bf[0][2*p][0] = r0; Bf[0][2*p][1] = r1;
                Bf[0][2*p+1][0] = r2; Bf[0][2*p+1][1] = r3;
                ldsm4(r0, r1, r2, r3, BS(cur,1)+r*40+c);
                Bf[1][2*p][0] = r0; Bf[1][2*p][1] = r1;
                Bf[1][2*p+1][0] = r2; Bf[1][2*p+1][1] = r3;
            }
#pragma unroll
            for (int mi = 0; mi < 4; mi++) {
                int r = wm*64 + mi*16 + (lane & 15);
                int c = kk + ((lane >> 4) << 3);
                uint32_t Ahf[4], Alf[4];
                ldsm4(Ahf[0], Ahf[1], Ahf[2], Ahf[3], AS(cur,0)+r*40+c);
                ldsm4(Alf[0], Alf[1], Alf[2], Alf[3], AS(cur,1)+r*40+c);
                // term-major: same-acc MMAs are 4 issues apart
#pragma unroll
                for (int ni = 0; ni < 4; ni++) mma16816(acc[mi][ni], Ahf, Bf[0][ni]);
#pragma unroll
                for (int ni = 0; ni < 4; ni++) mma16816(acc[mi][ni], Ahf, Bf[1][ni]);
#pragma unroll
                for (int ni = 0; ni < 4; ni++) mma16816(acc[mi][ni], Alf, Bf[0][ni]);
            }
        }
    }

    const int g = lane >> 2, tg2 = (lane & 3) * 2;
    if (Df) {
        float* Db = Df + (size_t)b*dBatch;
#pragma unroll
        for (int mi = 0; mi < 4; mi++)
#pragma unroll
            for (int ni = 0; ni < 4; ni++) {
                int row = M0 + wm*64 + mi*16 + g;
                int col = N0 + wn*32 + ni*8 + tg2;
                float b0 = bias ? bias[col] : 0.f;
                float b1 = bias ? bias[col+1] : 0.f;
                *(float2*)&Db[(size_t)row*dStride + col] =
                    make_float2(acc[mi][ni][0]+b0, acc[mi][ni][1]+b1);
                *(float2*)&Db[(size_t)(row+8)*dStride + col] =
                    make_float2(acc[mi][ni][2]+b0, acc[mi][ni][3]+b1);
            }
    } else {
        __nv_bfloat16* Dbh = Dh + (size_t)b*dBatch;
        __nv_bfloat16* Dbl = Dl + (size_t)b*dBatch;
#pragma unroll
        for (int mi = 0; mi < 4; mi++)
#pragma unroll
            for (int ni = 0; ni < 4; ni++) {
                int row = M0 + wm*64 + mi*16 + g;
                int col = N0 + wn*32 + ni*8 + tg2;
                __nv_bfloat16 h0,l0,h1,l1;
                __nv_bfloat162 hp, lp;
                split_bf16(acc[mi][ni][0], h0, l0);
                split_bf16(acc[mi][ni][1], h1, l1);
                hp.x = h0; hp.y = h1; lp.x = l0; lp.y = l1;
                *(__nv_bfloat162*)&Dbh[(size_t)row*dStride + col] = hp;
                *(__nv_bfloat162*)&Dbl[(size_t)row*dStride + col] = lp;
                split_bf16(acc[mi][ni][2], h0, l0);
                split_bf16(acc[mi][ni][3], h1, l1);
                hp.x = h0; hp.y = h1; lp.x = l0; lp.y = l1;
                *(__nv_bfloat162*)&Dbh[(size_t)(row+8)*dStride + col] = hp;
                *(__nv_bfloat162*)&Dbl[(size_t)(row+8)*dStride + col] = lp;
            }
    }
#undef AS
#undef BS
}

// =========================================================================
// merged weight split: Wk,Wq -> concatenated [Wk;Wq]; Wv, W2 separate
// =========================================================================
__global__ __launch_bounds__(256) void wsplit_all(
    const float* __restrict__ Wk, const float* __restrict__ Wq,
    const float* __restrict__ Wv, const float* __restrict__ W2)
{
    const int sel = blockIdx.y;
    const float* W = sel == 0 ? Wk : sel == 1 ? Wq : sel == 2 ? Wv : W2;
    __nv_bfloat16* h = sel == 0 ? g_wkqh : sel == 1 ? (g_wkqh + CC*CC)
                     : sel == 2 ? g_wvh : g_w2h;
    __nv_bfloat16* l = sel == 0 ? g_wkql : sel == 1 ? (g_wkql + CC*CC)
                     : sel == 2 ? g_wvl : g_w2l;
    int i = blockIdx.x * 256 + threadIdx.x;
    split_bf16(W[i], h[i], l[i]);
}

// =========================================================================
// x transpose + split: x [b][c][n] fp32 -> xT hi/lo [b][n][c]
// =========================================================================
__global__ __launch_bounds__(256) void xsplit_kernel(const float* __restrict__ x)
{
    __shared__ float Tm[32][33];
    const int b = blockIdx.z;
    const float* src = x + (size_t)b*CC*NN;
    __nv_bfloat16* dh = g_xth + (size_t)b*NN*CC;
    __nv_bfloat16* dl = g_xtl + (size_t)b*NN*CC;
    const int n0 = blockIdx.x * 32, c0 = blockIdx.y * 32;
    const int tx = threadIdx.x & 31, ty = threadIdx.x >> 5;

#pragma unroll
    for (int j = 0; j < 4; j++)
        Tm[ty + j*8][tx] = src[(size_t)(c0 + ty + j*8)*NN + n0 + tx];
    __syncthreads();
#pragma unroll
    for (int j = 0; j < 4; j++) {
        float v = Tm[tx][ty + j*8];
        int n = n0 + ty + j*8;
        __nv_bfloat16 h, l;
        split_bf16(v, h, l);
        dh[(size_t)n*CC + c0 + tx] = h;
        dl[(size_t)n*CC + c0 + tx] = l;
    }
}

// =========================================================================
// softmax over m of g_s; 288 threads x 8 contiguous elems, vectorized I/O
// =========================================================================
__global__ __launch_bounds__(288) void softmax_kernel()
{
    const int b = blockIdx.y, n = blockIdx.x;
    const float* row = g_s + ((size_t)b*NN + n) * NN;
    __nv_bfloat16* ph = g_ph + ((size_t)b*NN + n) * NN;
    __nv_bfloat16* pl = g_pl + ((size_t)b*NN + n) * NN;
    const int tid = threadIdx.x;
    const int base = tid * 8;

    float4 a0 = *(const float4*)&row[base];
    float4 a1 = *(const float4*)&row[base + 4];
    float v[8] = {a0.x, a0.y, a0.z, a0.w, a1.x, a1.y, a1.z, a1.w};

    float mx = v[0];
#pragma unroll
    for (int i = 1; i < 8; i++) mx = fmaxf(mx, v[i]);

    __shared__ float red[9];
#pragma unroll
    for (int off = 16; off; off >>= 1) mx = fmaxf(mx, __shfl_xor_sync(0xffffffffu, mx, off));
    if ((tid & 31) == 0) red[tid >> 5] = mx;
    __syncthreads();
    float gmx = red[0];
#pragma unroll
    for (int i = 1; i < 9; i++) gmx = fmaxf(gmx, red[i]);

    float s = 0.f;
#pragma unroll
    for (int i = 0; i < 8; i++) { v[i] = __expf(v[i] - gmx); s += v[i]; }
    __syncthreads();
#pragma unroll
    for (int off = 16; off; off >>= 1) s += __shfl_xor_sync(0xffffffffu, s, off);
    if ((tid & 31) == 0) red[tid >> 5] = s;
    __syncthreads();
    float tot = 0.f;
#pragma unroll
    for (int i = 0; i < 9; i++) tot += red[i];
    float inv = 1.0f / tot;

    __align__(16) __nv_bfloat16 h8[8], l8[8];
#pragma unroll
    for (int i = 0; i < 8; i++) split_bf16(v[i] * inv, h8[i], l8[i]);
    *(uint4*)&ph[base] = *(uint4*)h8;
    *(uint4*)&pl[base] = *(uint4*)l8;
}

// =========================================================================
// BatchNorm stats over y [b][n][o], two-phase
// =========================================================================
__global__ __launch_bounds__(256) void bnstats_part()
{
    const int tx = threadIdx.x & 31, ty = threadIdx.x >> 5;
    const int o = blockIdx.x * 32 + tx;
    const int slab = blockIdx.y;
    const int nbase = slab * 48;
    float s1 = 0.f, s2 = 0.f;
#pragma unroll
    for (int b = 0; b < BB; b++) {
        const float* yb = g_y + (size_t)b*NN*CC;
#pragma unroll
        for (int j = 0; j < 6; j++) {
            float v = yb[(size_t)(nbase + ty + j*8)*CC + o];
            s1 += v; s2 += v*v;
        }
    }
    __shared__ float r1[8][33], r2[8][33];
    r1[ty][tx] = s1; r2[ty][tx] = s2;
    __syncthreads();
    if (ty == 0) {
        float S1 = s1, S2 = s2;
#pragma unroll
        for (int i = 1; i < 8; i++) { S1 += r1[i][tx]; S2 += r2[i][tx]; }
        g_p1[slab][o] = S1;
        g_p2[slab][o] = S2;
    }
}

__global__ __launch_bounds__(256) void bnstats_fin()
{
    const int o = threadIdx.x;
    float S1 = 0.f, S2 = 0.f;
#pragma unroll
    for (int s = 0; s < 48; s++) { S1 += g_p1[s][o]; S2 += g_p2[s][o]; }
    const float invM = 1.0f / (float)(BB*NN);
    float mean = S1 * invM;
    float var  = S2 * invM - mean*mean;
    g_mean[o] = mean;
    g_rstd[o] = rsqrtf(var + 1e-5f);
}

// =========================================================================
// normalize + affine + transpose: y [b][n][o] -> out [b][o][n]
// =========================================================================
__global__ __launch_bounds__(256) void bnorm_kernel(
    const float* __restrict__ gamma, const float* __restrict__ beta,
    float* __restrict__ out)
{
    __shared__ float Tm[32][33];
    const int b = blockIdx.z;
    const int n0 = blockIdx.x * 32, o0 = blockIdx.y * 32;
    const int tx = threadIdx.x & 31, ty = threadIdx.x >> 5;
    const float* yb = g_y + (size_t)b*NN*CC;
#pragma unroll
    for (int j = 0; j < 4; j++)
        Tm[ty + j*8][tx] = yb[(size_t)(n0 + ty + j*8)*CC + o0 + tx];
    __syncthreads();
#pragma unroll
    for (int j = 0; j < 4; j++) {
        int o = o0 + ty + j*8;
        float sc = g_rstd[o] * gamma[o];
        float mb = g_mean[o];
        out[((size_t)b*CC + o)*NN + n0 + tx] = (Tm[tx][ty + j*8] - mb) * sc + beta[o];
    }
}

// =========================================================================
extern "C" void kernel_launch(void* const* d_in, const int* in_sizes, int n_in,
                              void* d_out, int out_size)
{
    (void)in_sizes; (void)n_in; (void)out_size;
    const float* x     = (const float*)d_in[0];
    const float* Wk    = (const float*)d_in[1];
    const float* Wq    = (const float*)d_in[2];
    const float* Wv    = (const float*)d_in[3];
    const float* W2    = (const float*)d_in[4];
    const float* b2    = (const float*)d_in[5];
    const float* gamma = (const float*)d_in[6];
    const float* beta  = (const float*)d_in[7];
    float* out = (float*)d_out;

    float *ps, *py;
    __nv_bfloat16 *pxth,*pxtl,*pkqth,*pkqtl,*pvh,*pvl,*path,*patl,*pph,*ppl;
    __nv_bfloat16 *pwkqh,*pwkql,*pwvh,*pwvl,*pw2h,*pw2l;
    cudaGetSymbolAddress((void**)&ps,    g_s);
    cudaGetSymbolAddress((void**)&py,    g_y);
    cudaGetSymbolAddress((void**)&pxth,  g_xth);  cudaGetSymbolAddress((void**)&pxtl,  g_xtl);
    cudaGetSymbolAddress((void**)&pkqth, g_kqth); cudaGetSymbolAddress((void**)&pkqtl, g_kqtl);
    cudaGetSymbolAddress((void**)&pvh,   g_vh);   cudaGetSymbolAddress((void**)&pvl,   g_vl);
    cudaGetSymbolAddress((void**)&path,  g_ath);  cudaGetSymbolAddress((void**)&patl,  g_atl);
    cudaGetSymbolAddress((void**)&pph,   g_ph);   cudaGetSymbolAddress((void**)&ppl,   g_pl);
    cudaGetSymbolAddress((void**)&pwkqh, g_wkqh); cudaGetSymbolAddress((void**)&pwkql, g_wkql);
    cudaGetSymbolAddress((void**)&pwvh,  g_wvh);  cudaGetSymbolAddress((void**)&pwvl,  g_wvl);
    cudaGetSymbolAddress((void**)&pw2h,  g_w2h);  cudaGetSymbolAddress((void**)&pw2l,  g_w2l);

    const int SMEM = 2*2*128*40*2*2;   // 81920 bytes
    cudaFuncSetAttribute(mma_split_gemm, cudaFuncAttributeMaxDynamicSharedMemorySize, SMEM);

    dim3 blk(256);

    wsplit_all<<<dim3(CC*CC/256, 4), blk>>>(Wk, Wq, Wv, W2);

    xsplit_kernel<<<dim3(NN/32, CC/32, BB), blk>>>(x);

    // kqT[b][n][o] = sum_c xT[n][c] * Wkq[o][c], o in [0,512)  (split out)
    mma_split_gemm<<<dim3(512/128, NN/128, BB), blk, SMEM>>>(
        pxth, pxtl, (size_t)NN*CC, CC,  pwkqh, pwkql, 0, CC,
        nullptr, pkqth, pkqtl, nullptr, (size_t)NN*512, 512, CC);

    // v[b][c][m] = sum_c' Wv[c][c'] * xT[m][c']   (split out)
    mma_split_gemm<<<dim3(NN/128, CC/128, BB), blk, SMEM>>>(
        pwvh, pwvl, 0, CC,  pxth, pxtl, (size_t)NN*CC, CC,
        nullptr, pvh, pvl, nullptr, (size_t)CC*NN, NN, CC);

    // scores[b][n][m] = sum_c kT[n][c]*qT[m][c]  (fp32 out)
    mma_split_gemm<<<dim3(NN/128, NN/128, BB), blk, SMEM>>>(
        pkqth, pkqtl, (size_t)NN*512, 512,
        pkqth + CC, pkqtl + CC, (size_t)NN*512, 512,
        ps, nullptr, nullptr, nullptr, (size_t)NN*NN, NN, CC);

    softmax_kernel<<<dim3(NN, BB), 288>>>();

    // attnT[b][n][c] = sum_m P[n][m]*v[c][m]  (split out)
    mma_split_gemm<<<dim3(CC/128, NN/128, BB), blk, SMEM>>>(
        pph, ppl, (size_t)NN*NN, NN,  pvh, pvl, (size_t)CC*NN, NN,
        nullptr, path, patl, nullptr, (size_t)NN*CC, CC, NN);

    // y[b][n][o] = sum_c attnT[n][c]*W2[o][c] + b2[o]  (fp32 out)
    mma_split_gemm<<<dim3(CC/128, NN/128, BB), blk, SMEM>>>(
        path, patl, (size_t)NN*CC, CC,  pw2h, pw2l, 0, CC,
        py, nullptr, nullptr, b2, (size_t)NN*CC, CC, CC);

    bnstats_part<<<dim3(CC/32, 48), blk>>>();
    bnstats_fin<<<1, CC>>>();

    bnorm_kernel<<<dim3(NN/32, CC/32, BB), blk>>>(gamma, beta, out);
}

// round 10
// speedup vs baseline: 3.2545x; 1.1722x over previous
#include <cuda_runtime.h>
#include <cuda_fp16.h>
#include <cstddef>
#include <cstdint>

#define BB 8
#define CC 256
#define NN 2304            // 48*48

// ---------------- scratch (static device memory: allowed) ----------------
__device__ __align__(16) float g_s[(size_t)BB*NN*NN];   // 170 MB scores
__device__ __align__(16) float g_y[(size_t)BB*NN*CC];   // y in [b][n][o]
__device__ float g_mean[CC];
__device__ float g_rstd[CC];
__device__ float g_p1[48][CC];
__device__ float g_p2[48][CC];

// fp16 operands (hi/lo split where needed)
__device__ __align__(16) __half g_xth[(size_t)BB*NN*CC],  g_xtl[(size_t)BB*NN*CC];   // xT [b][n][c]
__device__ __align__(16) __half g_kqth[(size_t)BB*NN*512], g_kqtl[(size_t)BB*NN*512]; // [b][n][k|q]
__device__ __align__(16) __half g_vh [(size_t)BB*CC*NN],  g_vl [(size_t)BB*CC*NN];   // v  [b][c][m]
__device__ __align__(16) __half g_at [(size_t)BB*NN*CC];                              // attnT single fp16
__device__ __align__(16) __half g_p  [(size_t)BB*NN*NN];                              // P single fp16
__device__ __align__(16) __half g_wkqh[2*CC*CC], g_wkql[2*CC*CC];  // [Wk;Wq]
__device__ __align__(16) __half g_wvh[CC*CC], g_wvl[CC*CC];
__device__ __align__(16) __half g_w2h[CC*CC], g_w2l[CC*CC];

// ---------------- helpers ----------------
__device__ __forceinline__ void split_h(float f, __half& h, __half& l) {
    h = __float2half_rn(f);
    l = __float2half_rn(f - __half2float(h));
}

__device__ __forceinline__ void ldsm4(uint32_t& r0, uint32_t& r1, uint32_t& r2, uint32_t& r3,
                                      const void* p) {
    uint32_t a = (uint32_t)__cvta_generic_to_shared(p);
    asm volatile("ldmatrix.sync.aligned.m8n8.x4.shared.b16 {%0,%1,%2,%3}, [%4];\n"
                 : "=r"(r0), "=r"(r1), "=r"(r2), "=r"(r3) : "r"(a));
}

__device__ __forceinline__ void mma16816(float* c, const uint32_t* a, const uint32_t* b) {
    asm volatile("mma.sync.aligned.m16n8k16.row.col.f32.f16.f16.f32 "
                 "{%0,%1,%2,%3}, {%4,%5,%6,%7}, {%8,%9}, {%0,%1,%2,%3};\n"
                 : "+f"(c[0]), "+f"(c[1]), "+f"(c[2]), "+f"(c[3])
                 : "r"(a[0]), "r"(a[1]), "r"(a[2]), "r"(a[3]), "r"(b[0]), "r"(b[1]));
}

__device__ __forceinline__ void cpasync16(void* s, const void* g) {
    uint32_t a = (uint32_t)__cvta_generic_to_shared(s);
    asm volatile("cp.async.cg.shared.global [%0], [%1], 16;\n" :: "r"(a), "l"(g));
}
__device__ __forceinline__ void cp_commit() { asm volatile("cp.async.commit_group;\n" ::); }

// =========================================================================
// split-fp16 tensor-core GEMM: D[b][M0+r][N0+c] = sum_k A[r][k]*B[c][k]
// TERMS bitmask: 1 = Ah*Bh (always), 2 = Ah*Bl, 4 = Al*Bh.
// Unused lo buffers are never loaded (smem traffic saved).
// block 128x128, 8 warps (2x4), warp tile 64x32, K-chunk 32, 2-stage cp.async.
// Epilogue: fp32 (+bias) if Df; split fp16 if Dh&&Dl; single fp16 if Dh only.
// =========================================================================
template<int TERMS>
__global__ __launch_bounds__(256, 2) void mma_split_gemm(
    const __half* __restrict__ Ah, const __half* __restrict__ Al,
    size_t aBatch, int aStride,
    const __half* __restrict__ Bh, const __half* __restrict__ Bl,
    size_t bBatch, int bStride,
    float* __restrict__ Df,
    __half* __restrict__ Dh, __half* __restrict__ Dl,
    const float* __restrict__ bias,
    size_t dBatch, int dStride, int Ktot)
{
    extern __shared__ __align__(16) __half smem[];
    __half* Abase = smem;                   // [2 stage][2 hi/lo][128*40]
    __half* Bbase = smem + 2*2*128*40;
#define AS(s,h) (Abase + ((s)*2+(h))*5120)
#define BS(s,h) (Bbase + ((s)*2+(h))*5120)

    const int b  = blockIdx.z;
    const int M0 = blockIdx.y * 128;
    const int N0 = blockIdx.x * 128;
    const int tid  = threadIdx.x;
    const int lane = tid & 31;
    const int warp = tid >> 5;
    const int wm = warp >> 2;     // 0..1
    const int wn = warp & 3;      // 0..3

    const __half* Abh = Ah + (size_t)b*aBatch + (size_t)M0*aStride;
    const __half* Abl = Al + (size_t)b*aBatch + (size_t)M0*aStride;
    const __half* Bbh = Bh + (size_t)b*bBatch + (size_t)N0*bStride;
    const __half* Bbl = Bl + (size_t)b*bBatch + (size_t)N0*bStride;

    float acc[4][4][4];
#pragma unroll
    for (int i = 0; i < 4; i++)
#pragma unroll
        for (int j = 0; j < 4; j++)
#pragma unroll
            for (int r = 0; r < 4; r++) acc[i][j][r] = 0.f;

    const int T = Ktot >> 5;   // K chunks of 32

    // prologue: load stage 0
    {
#pragma unroll
        for (int it = 0; it < 2; it++) {
            int t = tid + it*256;
            int row = t >> 2, seg = (t & 3) * 8;
            cpasync16(AS(0,0)+row*40+seg, Abh + (size_t)row*aStride + seg);
            if (TERMS & 4) cpasync16(AS(0,1)+row*40+seg, Abl + (size_t)row*aStride + seg);
            cpasync16(BS(0,0)+row*40+seg, Bbh + (size_t)row*bStride + seg);
            if (TERMS & 2) cpasync16(BS(0,1)+row*40+seg, Bbl + (size_t)row*bStride + seg);
        }
        cp_commit();
    }

    for (int t = 0; t < T; t++) {
        const int cur = t & 1;
        asm volatile("cp.async.wait_group 0;\n" ::);
        __syncthreads();

        if (t + 1 < T) {
            const int nxt = cur ^ 1;
            const int k0 = (t + 1) << 5;
#pragma unroll
            for (int it = 0; it < 2; it++) {
                int e = tid + it*256;
                int row = e >> 2, seg = (e & 3) * 8;
                cpasync16(AS(nxt,0)+row*40+seg, Abh + (size_t)row*aStride + k0 + seg);
                if (TERMS & 4) cpasync16(AS(nxt,1)+row*40+seg, Abl + (size_t)row*aStride + k0 + seg);
                cpasync16(BS(nxt,0)+row*40+seg, Bbh + (size_t)row*bStride + k0 + seg);
                if (TERMS & 2) cpasync16(BS(nxt,1)+row*40+seg, Bbl + (size_t)row*bStride + k0 + seg);
            }
            cp_commit();
        }

#pragma unroll
        for (int kk = 0; kk < 32; kk += 16) {
            uint32_t Bfh[4][2], Bfl[4][2];
#pragma unroll
            for (int p = 0; p < 2; p++) {
                int r = wn*32 + p*16 + ((lane >> 4) << 3) + (lane & 7);
                int c = kk + (((lane >> 3) & 1) << 3);
                uint32_t r0, r1, r2, r3;
                ldsm4(r0, r1, r2, r3, BS(cur,0)+r*40+c);
                Bfh[2*p][0] = r0; Bfh[2*p][1] = r1;
                Bfh[2*p+1][0] = r2; Bfh[2*p+1][1] = r3;
                if (TERMS & 2) {
                    ldsm4(r0, r1, r2, r3, BS(cur,1)+r*40+c);
                    Bfl[2*p][0] = r0; Bfl[2*p][1] = r1;
                    Bfl[2*p+1][0] = r2; Bfl[2*p+1][1] = r3;
                }
            }
#pragma unroll
            for (int mi = 0; mi < 4; mi++) {
                int r = wm*64 + mi*16 + (lane & 15);
                int c = kk + ((lane >> 4) << 3);
                uint32_t Ahf[4], Alf[4];
                ldsm4(Ahf[0], Ahf[1], Ahf[2], Ahf[3], AS(cur,0)+r*40+c);
                if (TERMS & 4) ldsm4(Alf[0], Alf[1], Alf[2], Alf[3], AS(cur,1)+r*40+c);
#pragma unroll
                for (int ni = 0; ni < 4; ni++) mma16816(acc[mi][ni], Ahf, Bfh[ni]);
                if (TERMS & 2) {
#pragma unroll
                    for (int ni = 0; ni < 4; ni++) mma16816(acc[mi][ni], Ahf, Bfl[ni]);
                }
                if (TERMS & 4) {
#pragma unroll
                    for (int ni = 0; ni < 4; ni++) mma16816(acc[mi][ni], Alf, Bfh[ni]);
                }
            }
        }
    }

    const int g = lane >> 2, tg2 = (lane & 3) * 2;
    if (Df) {
        float* Db = Df + (size_t)b*dBatch;
#pragma unroll
        for (int mi = 0; mi < 4; mi++)
#pragma unroll
            for (int ni = 0; ni < 4; ni++) {
                int row = M0 + wm*64 + mi*16 + g;
                int col = N0 + wn*32 + ni*8 + tg2;
                float b0 = bias ? bias[col] : 0.f;
                float b1 = bias ? bias[col+1] : 0.f;
                *(float2*)&Db[(size_t)row*dStride + col] =
                    make_float2(acc[mi][ni][0]+b0, acc[mi][ni][1]+b1);
                *(float2*)&Db[(size_t)(row+8)*dStride + col] =
                    make_float2(acc[mi][ni][2]+b0, acc[mi][ni][3]+b1);
            }
    } else if (Dl) {
        __half* Dbh = Dh + (size_t)b*dBatch;
        __half* Dbl = Dl + (size_t)b*dBatch;
#pragma unroll
        for (int mi = 0; mi < 4; mi++)
#pragma unroll
            for (int ni = 0; ni < 4; ni++) {
                int row = M0 + wm*64 + mi*16 + g;
                int col = N0 + wn*32 + ni*8 + tg2;
                __half h0,l0,h1,l1;
                split_h(acc[mi][ni][0], h0, l0);
                split_h(acc[mi][ni][1], h1, l1);
                *(__half2*)&Dbh[(size_t)row*dStride + col] = __halves2half2(h0, h1);
                *(__half2*)&Dbl[(size_t)row*dStride + col] = __halves2half2(l0, l1);
                split_h(acc[mi][ni][2], h0, l0);
                split_h(acc[mi][ni][3], h1, l1);
                *(__half2*)&Dbh[(size_t)(row+8)*dStride + col] = __halves2half2(h0, h1);
                *(__half2*)&Dbl[(size_t)(row+8)*dStride + col] = __halves2half2(l0, l1);
            }
    } else {
        __half* Dbh = Dh + (size_t)b*dBatch;
#pragma unroll
        for (int mi = 0; mi < 4; mi++)
#pragma unroll
            for (int ni = 0; ni < 4; ni++) {
                int row = M0 + wm*64 + mi*16 + g;
                int col = N0 + wn*32 + ni*8 + tg2;
                *(__half2*)&Dbh[(size_t)row*dStride + col] =
                    __halves2half2(__float2half_rn(acc[mi][ni][0]), __float2half_rn(acc[mi][ni][1]));
                *(__half2*)&Dbh[(size_t)(row+8)*dStride + col] =
                    __halves2half2(__float2half_rn(acc[mi][ni][2]), __float2half_rn(acc[mi][ni][3]));
            }
    }
#undef AS
#undef BS
}

// =========================================================================
// merged weight split: Wk,Wq -> concatenated [Wk;Wq]; Wv, W2 separate
// =========================================================================
__global__ __launch_bounds__(256) void wsplit_all(
    const float* __restrict__ Wk, const float* __restrict__ Wq,
    const float* __restrict__ Wv, const float* __restrict__ W2)
{
    const int sel = blockIdx.y;
    const float* W = sel == 0 ? Wk : sel == 1 ? Wq : sel == 2 ? Wv : W2;
    __half* h = sel == 0 ? g_wkqh : sel == 1 ? (g_wkqh + CC*CC)
              : sel == 2 ? g_wvh : g_w2h;
    __half* l = sel == 0 ? g_wkql : sel == 1 ? (g_wkql + CC*CC)
              : sel == 2 ? g_wvl : g_w2l;
    int i = blockIdx.x * 256 + threadIdx.x;
    split_h(W[i], h[i], l[i]);
}

// =========================================================================
// x transpose + split: x [b][c][n] fp32 -> xT hi/lo [b][n][c]
// =========================================================================
__global__ __launch_bounds__(256) void xsplit_kernel(const float* __restrict__ x)
{
    __shared__ float Tm[32][33];
    const int b = blockIdx.z;
    const float* src = x + (size_t)b*CC*NN;
    __half* dh = g_xth + (size_t)b*NN*CC;
    __half* dl = g_xtl + (size_t)b*NN*CC;
    const int n0 = blockIdx.x * 32, c0 = blockIdx.y * 32;
    const int tx = threadIdx.x & 31, ty = threadIdx.x >> 5;

#pragma unroll
    for (int j = 0; j < 4; j++)
        Tm[ty + j*8][tx] = src[(size_t)(c0 + ty + j*8)*NN + n0 + tx];
    __syncthreads();
#pragma unroll
    for (int j = 0; j < 4; j++) {
        float v = Tm[tx][ty + j*8];
        int n = n0 + ty + j*8;
        __half h, l;
        split_h(v, h, l);
        dh[(size_t)n*CC + c0 + tx] = h;
        dl[(size_t)n*CC + c0 + tx] = l;
    }
}

// =========================================================================
// softmax over m of g_s; 288 threads x 8 contiguous elems; single fp16 P out
// =========================================================================
__global__ __launch_bounds__(288) void softmax_kernel()
{
    const int b = blockIdx.y, n = blockIdx.x;
    const float* row = g_s + ((size_t)b*NN + n) * NN;
    __half* pp = g_p + ((size_t)b*NN + n) * NN;
    const int tid = threadIdx.x;
    const int base = tid * 8;

    float4 a0 = *(const float4*)&row[base];
    float4 a1 = *(const float4*)&row[base + 4];
    float v[8] = {a0.x, a0.y, a0.z, a0.w, a1.x, a1.y, a1.z, a1.w};

    float mx = v[0];
#pragma unroll
    for (int i = 1; i < 8; i++) mx = fmaxf(mx, v[i]);

    __shared__ float red[9];
#pragma unroll
    for (int off = 16; off; off >>= 1) mx = fmaxf(mx, __shfl_xor_sync(0xffffffffu, mx, off));
    if ((tid & 31) == 0) red[tid >> 5] = mx;
    __syncthreads();
    float gmx = red[0];
#pragma unroll
    for (int i = 1; i < 9; i++) gmx = fmaxf(gmx, red[i]);

    float s = 0.f;
#pragma unroll
    for (int i = 0; i < 8; i++) { v[i] = __expf(v[i] - gmx); s += v[i]; }
    __syncthreads();
#pragma unroll
    for (int off = 16; off; off >>= 1) s += __shfl_xor_sync(0xffffffffu, s, off);
    if ((tid & 31) == 0) red[tid >> 5] = s;
    __syncthreads();
    float tot = 0.f;
#pragma unroll
    for (int i = 0; i < 9; i++) tot += red[i];
    float inv = 1.0f / tot;

    __align__(16) __half h8[8];
#pragma unroll
    for (int i = 0; i < 8; i++) h8[i] = __float2half_rn(v[i] * inv);
    *(uint4*)&pp[base] = *(uint4*)h8;
}

// =========================================================================
// BatchNorm stats over y [b][n][o], two-phase
// =========================================================================
__global__ __launch_bounds__(256) void bnstats_part()
{
    const int tx = threadIdx.x & 31, ty = threadIdx.x >> 5;
    const int o = blockIdx.x * 32 + tx;
    const int slab = blockIdx.y;
    const int nbase = slab * 48;
    float s1 = 0.f, s2 = 0.f;
#pragma unroll
    for (int b = 0; b < BB; b++) {
        const float* yb = g_y + (size_t)b*NN*CC;
#pragma unroll
        for (int j = 0; j < 6; j++) {
            float v = yb[(size_t)(nbase + ty + j*8)*CC + o];
            s1 += v; s2 += v*v;
        }
    }
    __shared__ float r1[8][33], r2[8][33];
    r1[ty][tx] = s1; r2[ty][tx] = s2;
    __syncthreads();
    if (ty == 0) {
        float S1 = s1, S2 = s2;
#pragma unroll
        for (int i = 1; i < 8; i++) { S1 += r1[i][tx]; S2 += r2[i][tx]; }
        g_p1[slab][o] = S1;
        g_p2[slab][o] = S2;
    }
}

__global__ __launch_bounds__(256) void bnstats_fin()
{
    const int o = threadIdx.x;
    float S1 = 0.f, S2 = 0.f;
#pragma unroll
    for (int s = 0; s < 48; s++) { S1 += g_p1[s][o]; S2 += g_p2[s][o]; }
    const float invM = 1.0f / (float)(BB*NN);
    float mean = S1 * invM;
    float var  = S2 * invM - mean*mean;
    g_mean[o] = mean;
    g_rstd[o] = rsqrtf(var + 1e-5f);
}

// =========================================================================
// normalize + affine + transpose: y [b][n][o] -> out [b][o][n]
// =========================================================================
__global__ __launch_bounds__(256) void bnorm_kernel(
    const float* __restrict__ gamma, const float* __restrict__ beta,
    float* __restrict__ out)
{
    __shared__ float Tm[32][33];
    const int b = blockIdx.z;
    const int n0 = blockIdx.x * 32, o0 = blockIdx.y * 32;
    const int tx = threadIdx.x & 31, ty = threadIdx.x >> 5;
    const float* yb = g_y + (size_t)b*NN*CC;
#pragma unroll
    for (int j = 0; j < 4; j++)
        Tm[ty + j*8][tx] = yb[(size_t)(n0 + ty + j*8)*CC + o0 + tx];
    __syncthreads();
#pragma unroll
    for (int j = 0; j < 4; j++) {
        int o = o0 + ty + j*8;
        float sc = g_rstd[o] * gamma[o];
        float mb = g_mean[o];
        out[((size_t)b*CC + o)*NN + n0 + tx] = (Tm[tx][ty + j*8] - mb) * sc + beta[o];
    }
}

// =========================================================================
extern "C" void kernel_launch(void* const* d_in, const int* in_sizes, int n_in,
                              void* d_out, int out_size)
{
    (void)in_sizes; (void)n_in; (void)out_size;
    const float* x     = (const float*)d_in[0];
    const float* Wk    = (const float*)d_in[1];
    const float* Wq    = (const float*)d_in[2];
    const float* Wv    = (const float*)d_in[3];
    const float* W2    = (const float*)d_in[4];
    const float* b2    = (const float*)d_in[5];
    const float* gamma = (const float*)d_in[6];
    const float* beta  = (const float*)d_in[7];
    float* out = (float*)d_out;

    float *ps, *py;
    __half *pxth,*pxtl,*pkqth,*pkqtl,*pvh,*pvl,*pat,*pp;
    __half *pwkqh,*pwkql,*pwvh,*pwvl,*pw2h,*pw2l;
    cudaGetSymbolAddress((void**)&ps,    g_s);
    cudaGetSymbolAddress((void**)&py,    g_y);
    cudaGetSymbolAddress((void**)&pxth,  g_xth);  cudaGetSymbolAddress((void**)&pxtl,  g_xtl);
    cudaGetSymbolAddress((void**)&pkqth, g_kqth); cudaGetSymbolAddress((void**)&pkqtl, g_kqtl);
    cudaGetSymbolAddress((void**)&pvh,   g_vh);   cudaGetSymbolAddress((void**)&pvl,   g_vl);
    cudaGetSymbolAddress((void**)&pat,   g_at);   cudaGetSymbolAddress((void**)&pp,    g_p);
    cudaGetSymbolAddress((void**)&pwkqh, g_wkqh); cudaGetSymbolAddress((void**)&pwkql, g_wkql);
    cudaGetSymbolAddress((void**)&pwvh,  g_wvh);  cudaGetSymbolAddress((void**)&pwvl,  g_wvl);
    cudaGetSymbolAddress((void**)&pw2h,  g_w2h);  cudaGetSymbolAddress((void**)&pw2l,  g_w2l);

    const int SMEM = 2*2*128*40*2*2;   // 81920 bytes
    cudaFuncSetAttribute(mma_split_gemm<7>, cudaFuncAttributeMaxDynamicSharedMemorySize, SMEM);
    cudaFuncSetAttribute(mma_split_gemm<5>, cudaFuncAttributeMaxDynamicSharedMemorySize, SMEM);
    cudaFuncSetAttribute(mma_split_gemm<3>, cudaFuncAttributeMaxDynamicSharedMemorySize, SMEM);

    dim3 blk(256);

    wsplit_all<<<dim3(CC*CC/256, 4), blk>>>(Wk, Wq, Wv, W2);

    xsplit_kernel<<<dim3(NN/32, CC/32, BB), blk>>>(x);

    // kqT[b][n][o] = sum_c xT[n][c] * Wkq[o][c]  (3 terms, split out)
    mma_split_gemm<7><<<dim3(512/128, NN/128, BB), blk, SMEM>>>(
        pxth, pxtl, (size_t)NN*CC, CC,  pwkqh, pwkql, 0, CC,
        nullptr, pkqth, pkqtl, nullptr, (size_t)NN*512, 512, CC);

    // v[b][c][m] = sum_c' Wv[c][c'] * xT[m][c']  (2 terms: (Wh+Wl)*xh; split out)
    mma_split_gemm<5><<<dim3(NN/128, CC/128, BB), blk, SMEM>>>(
        pwvh, pwvl, 0, CC,  pxth, pxtl, (size_t)NN*CC, CC,
        nullptr, pvh, pvl, nullptr, (size_t)CC*NN, NN, CC);

    // scores[b][n][m] = sum_c kT[n][c]*qT[m][c]  (3 terms, fp32 out)
    mma_split_gemm<7><<<dim3(NN/128, NN/128, BB), blk, SMEM>>>(
        pkqth, pkqtl, (size_t)NN*512, 512,
        pkqth + CC, pkqtl + CC, (size_t)NN*512, 512,
        ps, nullptr, nullptr, nullptr, (size_t)NN*NN, NN, CC);

    softmax_kernel<<<dim3(NN, BB), 288>>>();

    // attnT[b][n][c] = sum_m P[n][m]*v[c][m]  (2 terms: P*(vh+vl); single fp16 out)
    mma_split_gemm<3><<<dim3(CC/128, NN/128, BB), blk, SMEM>>>(
        pp, pp, (size_t)NN*NN, NN,  pvh, pvl, (size_t)CC*NN, NN,
        nullptr, pat, nullptr, nullptr, (size_t)NN*CC, CC, NN);

    // y[b][n][o] = sum_c attnT[n][c]*W2[o][c] + b2[o]  (2 terms: attn*(W2h+W2l); fp32 out)
    mma_split_gemm<3><<<dim3(CC/128, NN/128, BB), blk, SMEM>>>(
        pat, pat, (size_t)NN*CC, CC,  pw2h, pw2l, 0, CC,
        py, nullptr, nullptr, b2, (size_t)NN*CC, CC, CC);

    bnstats_part<<<dim3(CC/32, 48), blk>>>();
    bnstats_fin<<<1, CC>>>();

    bnorm_kernel<<<dim3(NN/32, CC/32, BB), blk>>>(gamma, beta, out);
}

// round 11
// speedup vs baseline: 3.6388x; 1.1181x over previous
#include <cuda_runtime.h>
#include <cuda_fp16.h>
#include <cstddef>
#include <cstdint>

#define BB 8
#define CC 256
#define NN 2304            // 48*48

// ---------------- scratch (static device memory: allowed) ----------------
__device__ __align__(16) float g_s[(size_t)BB*NN*NN];   // 170 MB scores
__device__ __align__(16) float g_y[(size_t)BB*NN*CC];   // y in [b][n][o]
__device__ float g_mean[CC];
__device__ float g_rstd[CC];
__device__ float g_p1[48][CC];
__device__ float g_p2[48][CC];

// fp16 operands (hi/lo split where needed)
__device__ __align__(16) __half g_xth[(size_t)BB*NN*CC],  g_xtl[(size_t)BB*NN*CC];   // xT [b][n][c]
__device__ __align__(16) __half g_kqth[(size_t)BB*NN*512], g_kqtl[(size_t)BB*NN*512]; // [b][n][k|q]
__device__ __align__(16) __half g_v  [(size_t)BB*CC*NN];                              // v single fp16
__device__ __align__(16) __half g_at [(size_t)BB*NN*CC];                              // attnT single fp16
__device__ __align__(16) __half g_p  [(size_t)BB*NN*NN];                              // P single fp16
__device__ __align__(16) __half g_wkqh[2*CC*CC], g_wkql[2*CC*CC];  // [Wk;Wq]
__device__ __align__(16) __half g_wvh[CC*CC], g_wvl[CC*CC];
__device__ __align__(16) __half g_w2h[CC*CC], g_w2l[CC*CC];

// ---------------- helpers ----------------
__device__ __forceinline__ void split_h(float f, __half& h, __half& l) {
    h = __float2half_rn(f);
    l = __float2half_rn(f - __half2float(h));
}

__device__ __forceinline__ void ldsm4(uint32_t& r0, uint32_t& r1, uint32_t& r2, uint32_t& r3,
                                      const void* p) {
    uint32_t a = (uint32_t)__cvta_generic_to_shared(p);
    asm volatile("ldmatrix.sync.aligned.m8n8.x4.shared.b16 {%0,%1,%2,%3}, [%4];\n"
                 : "=r"(r0), "=r"(r1), "=r"(r2), "=r"(r3) : "r"(a));
}

__device__ __forceinline__ void mma16816(float* c, const uint32_t* a, const uint32_t* b) {
    asm volatile("mma.sync.aligned.m16n8k16.row.col.f32.f16.f16.f32 "
                 "{%0,%1,%2,%3}, {%4,%5,%6,%7}, {%8,%9}, {%0,%1,%2,%3};\n"
                 : "+f"(c[0]), "+f"(c[1]), "+f"(c[2]), "+f"(c[3])
                 : "r"(a[0]), "r"(a[1]), "r"(a[2]), "r"(a[3]), "r"(b[0]), "r"(b[1]));
}

__device__ __forceinline__ void cpasync16(void* s, const void* g) {
    uint32_t a = (uint32_t)__cvta_generic_to_shared(s);
    asm volatile("cp.async.cg.shared.global [%0], [%1], 16;\n" :: "r"(a), "l"(g));
}
__device__ __forceinline__ void cp_commit() { asm volatile("cp.async.commit_group;\n" ::); }

// =========================================================================
// split-fp16 tensor-core GEMM: D[b][M0+r][N0+c] = sum_k A[r][k]*B[c][k]
// TERMS bitmask: 1 = Ah*Bh (always), 2 = Ah*Bl, 4 = Al*Bh.
// Unused lo buffers are never loaded.
// block 128x128, 8 warps (2x4), warp tile 64x32, K-chunk 32, 2-stage cp.async.
// Epilogue: fp32 (+bias) if Df; split fp16 if Dh&&Dl; single fp16 if Dh only.
// =========================================================================
template<int TERMS>
__global__ __launch_bounds__(256, 2) void mma_split_gemm(
    const __half* __restrict__ Ah, const __half* __restrict__ Al,
    size_t aBatch, int aStride,
    const __half* __restrict__ Bh, const __half* __restrict__ Bl,
    size_t bBatch, int bStride,
    float* __restrict__ Df,
    __half* __restrict__ Dh, __half* __restrict__ Dl,
    const float* __restrict__ bias,
    size_t dBatch, int dStride, int Ktot)
{
    extern __shared__ __align__(16) __half smem[];
    __half* Abase = smem;                   // [2 stage][2 hi/lo][128*40]
    __half* Bbase = smem + 2*2*128*40;
#define AS(s,h) (Abase + ((s)*2+(h))*5120)
#define BS(s,h) (Bbase + ((s)*2+(h))*5120)

    const int b  = blockIdx.z;
    const int M0 = blockIdx.y * 128;
    const int N0 = blockIdx.x * 128;
    const int tid  = threadIdx.x;
    const int lane = tid & 31;
    const int warp = tid >> 5;
    const int wm = warp >> 2;     // 0..1
    const int wn = warp & 3;      // 0..3

    const __half* Abh = Ah + (size_t)b*aBatch + (size_t)M0*aStride;
    const __half* Abl = Al + (size_t)b*aBatch + (size_t)M0*aStride;
    const __half* Bbh = Bh + (size_t)b*bBatch + (size_t)N0*bStride;
    const __half* Bbl = Bl + (size_t)b*bBatch + (size_t)N0*bStride;

    float acc[4][4][4];
#pragma unroll
    for (int i = 0; i < 4; i++)
#pragma unroll
        for (int j = 0; j < 4; j++)
#pragma unroll
            for (int r = 0; r < 4; r++) acc[i][j][r] = 0.f;

    const int T = Ktot >> 5;   // K chunks of 32

    // prologue: load stage 0
    {
#pragma unroll
        for (int it = 0; it < 2; it++) {
            int t = tid + it*256;
            int row = t >> 2, seg = (t & 3) * 8;
            cpasync16(AS(0,0)+row*40+seg, Abh + (size_t)row*aStride + seg);
            if (TERMS & 4) cpasync16(AS(0,1)+row*40+seg, Abl + (size_t)row*aStride + seg);
            cpasync16(BS(0,0)+row*40+seg, Bbh + (size_t)row*bStride + seg);
            if (TERMS & 2) cpasync16(BS(0,1)+row*40+seg, Bbl + (size_t)row*bStride + seg);
        }
        cp_commit();
    }

    for (int t = 0; t < T; t++) {
        const int cur = t & 1;
        asm volatile("cp.async.wait_group 0;\n" ::);
        __syncthreads();

        if (t + 1 < T) {
            const int nxt = cur ^ 1;
            const int k0 = (t + 1) << 5;
#pragma unroll
            for (int it = 0; it < 2; it++) {
                int e = tid + it*256;
                int row = e >> 2, seg = (e & 3) * 8;
                cpasync16(AS(nxt,0)+row*40+seg, Abh + (size_t)row*aStride + k0 + seg);
                if (TERMS & 4) cpasync16(AS(nxt,1)+row*40+seg, Abl + (size_t)row*aStride + k0 + seg);
                cpasync16(BS(nxt,0)+row*40+seg, Bbh + (size_t)row*bStride + k0 + seg);
                if (TERMS & 2) cpasync16(BS(nxt,1)+row*40+seg, Bbl + (size_t)row*bStride + k0 + seg);
            }
            cp_commit();
        }

#pragma unroll
        for (int kk = 0; kk < 32; kk += 16) {
            uint32_t Bfh[4][2], Bfl[4][2];
#pragma unroll
            for (int p = 0; p < 2; p++) {
                int r = wn*32 + p*16 + ((lane >> 4) << 3) + (lane & 7);
                int c = kk + (((lane >> 3) & 1) << 3);
                uint32_t r0, r1, r2, r3;
                ldsm4(r0, r1, r2, r3, BS(cur,0)+r*40+c);
                Bfh[2*p][0] = r0; Bfh[2*p][1] = r1;
                Bfh[2*p+1][0] = r2; Bfh[2*p+1][1] = r3;
                if (TERMS & 2) {
                    ldsm4(r0, r1, r2, r3, BS(cur,1)+r*40+c);
                    Bfl[2*p][0] = r0; Bfl[2*p][1] = r1;
                    Bfl[2*p+1][0] = r2; Bfl[2*p+1][1] = r3;
                }
            }
#pragma unroll
            for (int mi = 0; mi < 4; mi++) {
                int r = wm*64 + mi*16 + (lane & 15);
                int c = kk + ((lane >> 4) << 3);
                uint32_t Ahf[4], Alf[4];
                ldsm4(Ahf[0], Ahf[1], Ahf[2], Ahf[3], AS(cur,0)+r*40+c);
                if (TERMS & 4) ldsm4(Alf[0], Alf[1], Alf[2], Alf[3], AS(cur,1)+r*40+c);
#pragma unroll
                for (int ni = 0; ni < 4; ni++) mma16816(acc[mi][ni], Ahf, Bfh[ni]);
                if (TERMS & 2) {
#pragma unroll
                    for (int ni = 0; ni < 4; ni++) mma16816(acc[mi][ni], Ahf, Bfl[ni]);
                }
                if (TERMS & 4) {
#pragma unroll
                    for (int ni = 0; ni < 4; ni++) mma16816(acc[mi][ni], Alf, Bfh[ni]);
                }
            }
        }
    }

    const int g = lane >> 2, tg2 = (lane & 3) * 2;
    if (Df) {
        float* Db = Df + (size_t)b*dBatch;
#pragma unroll
        for (int mi = 0; mi < 4; mi++)
#pragma unroll
            for (int ni = 0; ni < 4; ni++) {
                int row = M0 + wm*64 + mi*16 + g;
                int col = N0 + wn*32 + ni*8 + tg2;
                float b0 = bias ? bias[col] : 0.f;
                float b1 = bias ? bias[col+1] : 0.f;
                *(float2*)&Db[(size_t)row*dStride + col] =
                    make_float2(acc[mi][ni][0]+b0, acc[mi][ni][1]+b1);
                *(float2*)&Db[(size_t)(row+8)*dStride + col] =
                    make_float2(acc[mi][ni][2]+b0, acc[mi][ni][3]+b1);
            }
    } else if (Dl) {
        __half* Dbh = Dh + (size_t)b*dBatch;
        __half* Dbl = Dl + (size_t)b*dBatch;
#pragma unroll
        for (int mi = 0; mi < 4; mi++)
#pragma unroll
            for (int ni = 0; ni < 4; ni++) {
                int row = M0 + wm*64 + mi*16 + g;
                int col = N0 + wn*32 + ni*8 + tg2;
                __half h0,l0,h1,l1;
                split_h(acc[mi][ni][0], h0, l0);
                split_h(acc[mi][ni][1], h1, l1);
                *(__half2*)&Dbh[(size_t)row*dStride + col] = __halves2half2(h0, h1);
                *(__half2*)&Dbl[(size_t)row*dStride + col] = __halves2half2(l0, l1);
                split_h(acc[mi][ni][2], h0, l0);
                split_h(acc[mi][ni][3], h1, l1);
                *(__half2*)&Dbh[(size_t)(row+8)*dStride + col] = __halves2half2(h0, h1);
                *(__half2*)&Dbl[(size_t)(row+8)*dStride + col] = __halves2half2(l0, l1);
            }
    } else {
        __half* Dbh = Dh + (size_t)b*dBatch;
#pragma unroll
        for (int mi = 0; mi < 4; mi++)
#pragma unroll
            for (int ni = 0; ni < 4; ni++) {
                int row = M0 + wm*64 + mi*16 + g;
                int col = N0 + wn*32 + ni*8 + tg2;
                *(__half2*)&Dbh[(size_t)row*dStride + col] =
                    __halves2half2(__float2half_rn(acc[mi][ni][0]), __float2half_rn(acc[mi][ni][1]));
                *(__half2*)&Dbh[(size_t)(row+8)*dStride + col] =
                    __halves2half2(__float2half_rn(acc[mi][ni][2]), __float2half_rn(acc[mi][ni][3]));
            }
    }
#undef AS
#undef BS
}

// =========================================================================
// merged weight split: Wk,Wq -> concatenated [Wk;Wq]; Wv, W2 separate
// =========================================================================
__global__ __launch_bounds__(256) void wsplit_all(
    const float* __restrict__ Wk, const float* __restrict__ Wq,
    const float* __restrict__ Wv, const float* __restrict__ W2)
{
    const int sel = blockIdx.y;
    const float* W = sel == 0 ? Wk : sel == 1 ? Wq : sel == 2 ? Wv : W2;
    __half* h = sel == 0 ? g_wkqh : sel == 1 ? (g_wkqh + CC*CC)
              : sel == 2 ? g_wvh : g_w2h;
    __half* l = sel == 0 ? g_wkql : sel == 1 ? (g_wkql + CC*CC)
              : sel == 2 ? g_wvl : g_w2l;
    int i = blockIdx.x * 256 + threadIdx.x;
    split_h(W[i], h[i], l[i]);
}

// =========================================================================
// x transpose + split: x [b][c][n] fp32 -> xT hi/lo [b][n][c]
// =========================================================================
__global__ __launch_bounds__(256) void xsplit_kernel(const float* __restrict__ x)
{
    __shared__ float Tm[32][33];
    const int b = blockIdx.z;
    const float* src = x + (size_t)b*CC*NN;
    __half* dh = g_xth + (size_t)b*NN*CC;
    __half* dl = g_xtl + (size_t)b*NN*CC;
    const int n0 = blockIdx.x * 32, c0 = blockIdx.y * 32;
    const int tx = threadIdx.x & 31, ty = threadIdx.x >> 5;

#pragma unroll
    for (int j = 0; j < 4; j++)
        Tm[ty + j*8][tx] = src[(size_t)(c0 + ty + j*8)*NN + n0 + tx];
    __syncthreads();
#pragma unroll
    for (int j = 0; j < 4; j++) {
        float v = Tm[tx][ty + j*8];
        int n = n0 + ty + j*8;
        __half h, l;
        split_h(v, h, l);
        dh[(size_t)n*CC + c0 + tx] = h;
        dl[(size_t)n*CC + c0 + tx] = l;
    }
}

// =========================================================================
// softmax over m of g_s; 288 threads x 8 contiguous elems; single fp16 P out
// =========================================================================
__global__ __launch_bounds__(288) void softmax_kernel()
{
    const int b = blockIdx.y, n = blockIdx.x;
    const float* row = g_s + ((size_t)b*NN + n) * NN;
    __half* pp = g_p + ((size_t)b*NN + n) * NN;
    const int tid = threadIdx.x;
    const int base = tid * 8;

    float4 a0 = *(const float4*)&row[base];
    float4 a1 = *(const float4*)&row[base + 4];
    float v[8] = {a0.x, a0.y, a0.z, a0.w, a1.x, a1.y, a1.z, a1.w};

    float mx = v[0];
#pragma unroll
    for (int i = 1; i < 8; i++) mx = fmaxf(mx, v[i]);

    __shared__ float red[9];
#pragma unroll
    for (int off = 16; off; off >>= 1) mx = fmaxf(mx, __shfl_xor_sync(0xffffffffu, mx, off));
    if ((tid & 31) == 0) red[tid >> 5] = mx;
    __syncthreads();
    float gmx = red[0];
#pragma unroll
    for (int i = 1; i < 9; i++) gmx = fmaxf(gmx, red[i]);

    float s = 0.f;
#pragma unroll
    for (int i = 0; i < 8; i++) { v[i] = __expf(v[i] - gmx); s += v[i]; }
    __syncthreads();
#pragma unroll
    for (int off = 16; off; off >>= 1) s += __shfl_xor_sync(0xffffffffu, s, off);
    if ((tid & 31) == 0) red[tid >> 5] = s;
    __syncthreads();
    float tot = 0.f;
#pragma unroll
    for (int i = 0; i < 9; i++) tot += red[i];
    float inv = 1.0f / tot;

    __align__(16) __half h8[8];
#pragma unroll
    for (int i = 0; i < 8; i++) h8[i] = __float2half_rn(v[i] * inv);
    *(uint4*)&pp[base] = *(uint4*)h8;
}

// =========================================================================
// BatchNorm stats over y [b][n][o], two-phase
// =========================================================================
__global__ __launch_bounds__(256) void bnstats_part()
{
    const int tx = threadIdx.x & 31, ty = threadIdx.x >> 5;
    const int o = blockIdx.x * 32 + tx;
    const int slab = blockIdx.y;
    const int nbase = slab * 48;
    float s1 = 0.f, s2 = 0.f;
#pragma unroll
    for (int b = 0; b < BB; b++) {
        const float* yb = g_y + (size_t)b*NN*CC;
#pragma unroll
        for (int j = 0; j < 6; j++) {
            float v = yb[(size_t)(nbase + ty + j*8)*CC + o];
            s1 += v; s2 += v*v;
        }
    }
    __shared__ float r1[8][33], r2[8][33];
    r1[ty][tx] = s1; r2[ty][tx] = s2;
    __syncthreads();
    if (ty == 0) {
        float S1 = s1, S2 = s2;
#pragma unroll
        for (int i = 1; i < 8; i++) { S1 += r1[i][tx]; S2 += r2[i][tx]; }
        g_p1[slab][o] = S1;
        g_p2[slab][o] = S2;
    }
}

__global__ __launch_bounds__(256) void bnstats_fin()
{
    const int o = threadIdx.x;
    float S1 = 0.f, S2 = 0.f;
#pragma unroll
    for (int s = 0; s < 48; s++) { S1 += g_p1[s][o]; S2 += g_p2[s][o]; }
    const float invM = 1.0f / (float)(BB*NN);
    float mean = S1 * invM;
    float var  = S2 * invM - mean*mean;
    g_mean[o] = mean;
    g_rstd[o] = rsqrtf(var + 1e-5f);
}

// =========================================================================
// normalize + affine + transpose: y [b][n][o] -> out [b][o][n]
// =========================================================================
__global__ __launch_bounds__(256) void bnorm_kernel(
    const float* __restrict__ gamma, const float* __restrict__ beta,
    float* __restrict__ out)
{
    __shared__ float Tm[32][33];
    const int b = blockIdx.z;
    const int n0 = blockIdx.x * 32, o0 = blockIdx.y * 32;
    const int tx = threadIdx.x & 31, ty = threadIdx.x >> 5;
    const float* yb = g_y + (size_t)b*NN*CC;
#pragma unroll
    for (int j = 0; j < 4; j++)
        Tm[ty + j*8][tx] = yb[(size_t)(n0 + ty + j*8)*CC + o0 + tx];
    __syncthreads();
#pragma unroll
    for (int j = 0; j < 4; j++) {
        int o = o0 + ty + j*8;
        float sc = g_rstd[o] * gamma[o];
        float mb = g_mean[o];
        out[((size_t)b*CC + o)*NN + n0 + tx] = (Tm[tx][ty + j*8] - mb) * sc + beta[o];
    }
}

// =========================================================================
extern "C" void kernel_launch(void* const* d_in, const int* in_sizes, int n_in,
                              void* d_out, int out_size)
{
    (void)in_sizes; (void)n_in; (void)out_size;
    const float* x     = (const float*)d_in[0];
    const float* Wk    = (const float*)d_in[1];
    const float* Wq    = (const float*)d_in[2];
    const float* Wv    = (const float*)d_in[3];
    const float* W2    = (const float*)d_in[4];
    const float* b2    = (const float*)d_in[5];
    const float* gamma = (const float*)d_in[6];
    const float* beta  = (const float*)d_in[7];
    float* out = (float*)d_out;

    float *ps, *py;
    __half *pxth,*pxtl,*pkqth,*pkqtl,*pv,*pat,*pp;
    __half *pwkqh,*pwkql,*pwvh,*pwvl,*pw2h,*pw2l;
    cudaGetSymbolAddress((void**)&ps,    g_s);
    cudaGetSymbolAddress((void**)&py,    g_y);
    cudaGetSymbolAddress((void**)&pxth,  g_xth);  cudaGetSymbolAddress((void**)&pxtl,  g_xtl);
    cudaGetSymbolAddress((void**)&pkqth, g_kqth); cudaGetSymbolAddress((void**)&pkqtl, g_kqtl);
    cudaGetSymbolAddress((void**)&pv,    g_v);
    cudaGetSymbolAddress((void**)&pat,   g_at);   cudaGetSymbolAddress((void**)&pp,    g_p);
    cudaGetSymbolAddress((void**)&pwkqh, g_wkqh); cudaGetSymbolAddress((void**)&pwkql, g_wkql);
    cudaGetSymbolAddress((void**)&pwvh,  g_wvh);  cudaGetSymbolAddress((void**)&pwvl,  g_wvl);
    cudaGetSymbolAddress((void**)&pw2h,  g_w2h);  cudaGetSymbolAddress((void**)&pw2l,  g_w2l);

    const int SMEM = 2*2*128*40*2*2;   // 81920 bytes
    cudaFuncSetAttribute(mma_split_gemm<7>, cudaFuncAttributeMaxDynamicSharedMemorySize, SMEM);
    cudaFuncSetAttribute(mma_split_gemm<5>, cudaFuncAttributeMaxDynamicSharedMemorySize, SMEM);
    cudaFuncSetAttribute(mma_split_gemm<3>, cudaFuncAttributeMaxDynamicSharedMemorySize, SMEM);
    cudaFuncSetAttribute(mma_split_gemm<1>, cudaFuncAttributeMaxDynamicSharedMemorySize, SMEM);

    dim3 blk(256);

    wsplit_all<<<dim3(CC*CC/256, 4), blk>>>(Wk, Wq, Wv, W2);

    xsplit_kernel<<<dim3(NN/32, CC/32, BB), blk>>>(x);

    // kqT[b][n][o] = sum_c xT[n][c] * Wkq[o][c]  (3 terms, split out)
    mma_split_gemm<7><<<dim3(512/128, NN/128, BB), blk, SMEM>>>(
        pxth, pxtl, (size_t)NN*CC, CC,  pwkqh, pwkql, 0, CC,
        nullptr, pkqth, pkqtl, nullptr, (size_t)NN*512, 512, CC);

    // v[b][c][m] = sum_c' Wv[c][c'] * xT[m][c']  (2 terms: (Wh+Wl)*xh; SINGLE fp16 out)
    mma_split_gemm<5><<<dim3(NN/128, CC/128, BB), blk, SMEM>>>(
        pwvh, pwvl, 0, CC,  pxth, pxtl, (size_t)NN*CC, CC,
        nullptr, pv, nullptr, nullptr, (size_t)CC*NN, NN, CC);

    // scores[b][n][m] = sum_c kT[n][c]*qT[m][c]  (3 terms, fp32 out)
    mma_split_gemm<7><<<dim3(NN/128, NN/128, BB), blk, SMEM>>>(
        pkqth, pkqtl, (size_t)NN*512, 512,
        pkqth + CC, pkqtl + CC, (size_t)NN*512, 512,
        ps, nullptr, nullptr, nullptr, (size_t)NN*NN, NN, CC);

    softmax_kernel<<<dim3(NN, BB), 288>>>();

    // attnT[b][n][c] = sum_m P[n][m]*v[c][m]  (1 term: single-fp16 P x single-fp16 v)
    mma_split_gemm<1><<<dim3(CC/128, NN/128, BB), blk, SMEM>>>(
        pp, nullptr, (size_t)NN*NN, NN,  pv, nullptr, (size_t)CC*NN, NN,
        nullptr, pat, nullptr, nullptr, (size_t)NN*CC, CC, NN);

    // y[b][n][o] = sum_c attnT[n][c]*W2[o][c] + b2[o]  (2 terms; fp32 out)
    mma_split_gemm<3><<<dim3(CC/128, NN/128, BB), blk, SMEM>>>(
        pat, nullptr, (size_t)NN*CC, CC,  pw2h, pw2l, 0, CC,
        py, nullptr, nullptr, b2, (size_t)NN*CC, CC, CC);

    bnstats_part<<<dim3(CC/32, 48), blk>>>();
    bnstats_fin<<<1, CC>>>();

    bnorm_kernel<<<dim3(NN/32, CC/32, BB), blk>>>(gamma, beta, out);
}